// round 13
// baseline (speedup 1.0000x reference)
#include <cuda_runtime.h>
#include <cuda_bf16.h>
#include <cstdint>
#include <math.h>

#if defined(__CUDA_ARCH_FEAT_SM103_ALL) || defined(__CUDA_ARCH_FEAT_SM100_ALL)
#define TC_PATH 1
#else
#define TC_PATH 0
#endif

#define BB  32
#define SS  1024
#define DD  256
#define HH  8
#define DKK 32

// ---------------- fp32 scratch (baseline fallback path) ----------------
__device__ float g_q[BB*HH*SS*DKK];
__device__ float g_k[BB*HH*SS*DKK];
__device__ float g_v[BB*HH*SS*DKK];

// ---------------- split-bf16 scratch (tcgen05 path) ----------------
__device__ __nv_bfloat16 g_Qs[BB*HH*SS*64];
__device__ __nv_bfloat16 g_Ksx[BB*HH*SS*64];
__device__ __nv_bfloat16 g_Vt[BB*HH*8*32*256];

// ======================= common helpers =======================
__device__ __forceinline__ uint32_t smem_u32(const void* p) {
    uint32_t a;
    asm("{ .reg .u64 t; cvta.to.shared.u64 t, %1; cvt.u32.u64 %0, t; }" : "=r"(a) : "l"(p));
    return a;
}
__device__ __forceinline__ uint32_t sw128(uint32_t b) { return b ^ ((b >> 3) & 0x70); }
__device__ __forceinline__ uint32_t bf2u(__nv_bfloat162 v) {
    union { __nv_bfloat162 b; uint32_t u; } cv; cv.b = v; return cv.u;
}

#if TC_PATH
// ======================= tcgen05 helpers (sm_103a only) =======================
__device__ __forceinline__ uint32_t elect_one() {
    uint32_t pred;
    asm volatile("{\n\t.reg .pred p;\n\telect.sync _|p, 0xFFFFFFFF;\n\tselp.b32 %0, 1, 0, p;\n\t}" : "=r"(pred));
    return pred;
}
#define TCGEN05_ALLOC(sa, n) \
    asm volatile("tcgen05.alloc.cta_group::1.sync.aligned.shared::cta.b32 [%0], %1;" \
        :: "r"((uint32_t)(sa)), "r"((uint32_t)(n)) : "memory")
#define TCGEN05_DEALLOC(t, n) \
    asm volatile("tcgen05.dealloc.cta_group::1.sync.aligned.b32 %0, %1;" :: "r"(t), "r"((uint32_t)(n)))
#define TCGEN05_COMMIT(mb) \
    asm volatile("tcgen05.commit.cta_group::1.mbarrier::arrive::one.shared::cluster.b64 [%0];" \
        :: "r"((uint32_t)(mb)) : "memory")
#define TCGEN05_WAIT_LD()  asm volatile("tcgen05.wait::ld.sync.aligned;" ::: "memory")
#define TCGEN05_WAIT_ST()  asm volatile("tcgen05.wait::st.sync.aligned;" ::: "memory")
#define TCGEN05_FENCE_AFTER()  asm volatile("tcgen05.fence::after_thread_sync;" ::: "memory")
#define TCGEN05_FENCE_BEFORE() asm volatile("tcgen05.fence::before_thread_sync;" ::: "memory")
#define FENCE_ASYNC_SHARED() asm volatile("fence.proxy.async.shared::cta;" ::: "memory")
#define MBARRIER_INIT(mb, c) \
    asm volatile("mbarrier.init.shared.b64 [%0], %1;" :: "r"((uint32_t)(mb)), "r"((uint32_t)(c)) : "memory")
#define MBARRIER_WAIT_PARITY(mb, ph) do { \
    uint32_t _m = (uint32_t)(mb), _p = (uint32_t)(ph), _d; \
    asm volatile("{\n\t.reg .pred p;\n\t" \
        "mbarrier.try_wait.parity.acquire.cta.shared::cta.b64 p, [%1], %2;\n\t" \
        "selp.b32 %0, 1, 0, p;\n\t}" : "=r"(_d) : "r"(_m), "r"(_p) : "memory"); \
    if (!_d) { \
        asm volatile("{\n\t.reg .pred P1;\n\t" \
            "WL_%=:\n\t" \
            "mbarrier.try_wait.parity.acquire.cta.shared::cta.b64 P1, [%0], %1, 0x989680;\n\t" \
            "@P1 bra.uni WD_%=;\n\tbra.uni WL_%=;\n\tWD_%=:\n\t}" \
            :: "r"(_m), "r"(_p) : "memory"); \
    } } while (0)
#define TCGEN05_LD_X32(r, ta) \
    asm volatile("tcgen05.ld.sync.aligned.32x32b.x32.b32 " \
        "{%0, %1, %2, %3, %4, %5, %6, %7, %8, %9, %10, %11, %12, %13, %14, %15, " \
        " %16, %17, %18, %19, %20, %21, %22, %23, %24, %25, %26, %27, %28, %29, %30, %31}, [%32];" \
        : "=r"((r)[0]),  "=r"((r)[1]),  "=r"((r)[2]),  "=r"((r)[3]), \
          "=r"((r)[4]),  "=r"((r)[5]),  "=r"((r)[6]),  "=r"((r)[7]), \
          "=r"((r)[8]),  "=r"((r)[9]),  "=r"((r)[10]), "=r"((r)[11]), \
          "=r"((r)[12]), "=r"((r)[13]), "=r"((r)[14]), "=r"((r)[15]), \
          "=r"((r)[16]), "=r"((r)[17]), "=r"((r)[18]), "=r"((r)[19]), \
          "=r"((r)[20]), "=r"((r)[21]), "=r"((r)[22]), "=r"((r)[23]), \
          "=r"((r)[24]), "=r"((r)[25]), "=r"((r)[26]), "=r"((r)[27]), \
          "=r"((r)[28]), "=r"((r)[29]), "=r"((r)[30]), "=r"((r)[31]) \
        : "r"(ta))
#define TCGEN05_LD_X16(r, ta) \
    asm volatile("tcgen05.ld.sync.aligned.32x32b.x16.b32 " \
        "{%0, %1, %2, %3, %4, %5, %6, %7, %8, %9, %10, %11, %12, %13, %14, %15}, [%16];" \
        : "=r"((r)[0]),  "=r"((r)[1]),  "=r"((r)[2]),  "=r"((r)[3]), \
          "=r"((r)[4]),  "=r"((r)[5]),  "=r"((r)[6]),  "=r"((r)[7]), \
          "=r"((r)[8]),  "=r"((r)[9]),  "=r"((r)[10]), "=r"((r)[11]), \
          "=r"((r)[12]), "=r"((r)[13]), "=r"((r)[14]), "=r"((r)[15]) \
        : "r"(ta))
#define TCGEN05_ST_X32(ta, r) \
    asm volatile("tcgen05.st.sync.aligned.32x32b.x32.b32 [%0], " \
        "{%1, %2, %3, %4, %5, %6, %7, %8, %9, %10, %11, %12, %13, %14, %15, %16, " \
        " %17, %18, %19, %20, %21, %22, %23, %24, %25, %26, %27, %28, %29, %30, %31, %32};" \
        :: "r"(ta), \
           "r"((r)[0]),  "r"((r)[1]),  "r"((r)[2]),  "r"((r)[3]), \
           "r"((r)[4]),  "r"((r)[5]),  "r"((r)[6]),  "r"((r)[7]), \
           "r"((r)[8]),  "r"((r)[9]),  "r"((r)[10]), "r"((r)[11]), \
           "r"((r)[12]), "r"((r)[13]), "r"((r)[14]), "r"((r)[15]), \
           "r"((r)[16]), "r"((r)[17]), "r"((r)[18]), "r"((r)[19]), \
           "r"((r)[20]), "r"((r)[21]), "r"((r)[22]), "r"((r)[23]), \
           "r"((r)[24]), "r"((r)[25]), "r"((r)[26]), "r"((r)[27]), \
           "r"((r)[28]), "r"((r)[29]), "r"((r)[30]), "r"((r)[31]) \
        : "memory")

static constexpr uint64_t DESC_BASE_SW128 =
    (uint64_t(2) << 61) | (uint64_t(1) << 46) | (uint64_t(64) << 32) | (uint64_t(1) << 16);
#define MAKE_DESC(a) (DESC_BASE_SW128 | ((uint64_t)((a) >> 4) & 0x3FFF))

__device__ __forceinline__ void mma_f16_ss(uint32_t d, uint64_t ad, uint64_t bd,
                                           uint32_t idesc, bool acc) {
    uint32_t en = acc ? 1u : 0u, z = 0u;
    asm volatile(
        "{\n\t.reg .pred p;\n\tsetp.ne.u32 p, %4, 0;\n\t"
        "tcgen05.mma.cta_group::1.kind::f16 [%0], %1, %2, %3, {%5, %5, %5, %5}, p;\n\t}"
        :: "r"(d), "l"(ad), "l"(bd), "r"(idesc), "r"(en), "r"(z) : "memory");
}
__device__ __forceinline__ void mma_f16_ts(uint32_t d, uint32_t a, uint64_t bd,
                                           uint32_t idesc, bool acc) {
    uint32_t en = acc ? 1u : 0u, z = 0u;
    asm volatile(
        "{\n\t.reg .pred p;\n\tsetp.ne.u32 p, %4, 0;\n\t"
        "tcgen05.mma.cta_group::1.kind::f16 [%0], [%1], %2, %3, {%5, %5, %5, %5}, p;\n\t}"
        :: "r"(d), "r"(a), "l"(bd), "r"(idesc), "r"(en), "r"(z) : "memory");
}

// idesc: F32 acc | bf16 A | bf16 B | N | M=128
#define IDESC_QK (0x10u | 0x80u | 0x400u | (16u << 17) | (8u << 24))   /* N=128 */
#define IDESC_PV (0x10u | 0x80u | 0x400u | (4u  << 17) | (8u << 24))   /* N=32  */
#define IDESC_PJ (0x10u | 0x80u | 0x400u | (32u << 17) | (8u << 24))   /* N=256 */

// TS-mode 6-term split-bf16 QK (Q in TMEM: hi @ +0, lo @ +16 cols), commit
__device__ __forceinline__ void issue_qk_ts(uint32_t dS, uint32_t qt, uint64_t kd, uint32_t mb) {
    mma_f16_ts(dS, qt + 0,  kd + 0, IDESC_QK, false);   // hi.hi
    mma_f16_ts(dS, qt + 8,  kd + 2, IDESC_QK, true);
    mma_f16_ts(dS, qt + 0,  kd + 4, IDESC_QK, true);    // hi.lo
    mma_f16_ts(dS, qt + 8,  kd + 6, IDESC_QK, true);
    mma_f16_ts(dS, qt + 16, kd + 0, IDESC_QK, true);    // lo.hi
    mma_f16_ts(dS, qt + 24, kd + 2, IDESC_QK, true);
    TCGEN05_COMMIT(mb);
}
// 24-term split-bf16 PV, then commit
__device__ __forceinline__ void issue_pv(uint32_t dO, uint64_t pd, uint64_t vd,
                                         bool first, uint32_t mb) {
    #pragma unroll
    for (int t = 0; t < 8; t++) {
        uint64_t po = (uint64_t)((t >> 2)*1024 + (t & 3)*2);
        uint64_t vo = (uint64_t)((t >> 2)*256  + (t & 3)*2);
        mma_f16_ss(dO, pd + po, vd + vo, IDESC_PV, !(first && t == 0));
    }
    #pragma unroll
    for (int t = 0; t < 8; t++) {
        uint64_t po = (uint64_t)((t >> 2)*1024 + (t & 3)*2);
        int t2 = t + 8;
        uint64_t vo = (uint64_t)((t2 >> 2)*256 + (t2 & 3)*2);
        mma_f16_ss(dO, pd + po, vd + vo, IDESC_PV, true);
    }
    #pragma unroll
    for (int t = 0; t < 8; t++) {
        int t2 = t + 8;
        uint64_t po = (uint64_t)((t2 >> 2)*1024 + (t2 & 3)*2);
        uint64_t vo = (uint64_t)((t >> 2)*256   + (t & 3)*2);
        mma_f16_ss(dO, pd + po, vd + vo, IDESC_PV, true);
    }
    TCGEN05_COMMIT(mb);
}

__device__ __forceinline__ uint32_t p_off(int r, int c) {
    uint32_t byte = ((uint32_t)(r >> 3) + (uint32_t)(c >> 6)*16u)*1024u
                  + (uint32_t)(r & 7)*128u + (uint32_t)(c & 63)*2u;
    return sw128(byte);
}
__device__ __forceinline__ uint32_t v_off(int n, int c) {
    uint32_t byte = ((uint32_t)(n >> 3) + (uint32_t)(c >> 6)*4u)*1024u
                  + (uint32_t)(n & 7)*128u + (uint32_t)(c & 63)*2u;
    return sw128(byte);
}
__device__ __forceinline__ uint32_t b_off(int n, int c) {
    uint32_t byte = ((uint32_t)(n >> 3) + (uint32_t)(c >> 6)*32u)*1024u
                  + (uint32_t)(n & 7)*128u + (uint32_t)(c & 63)*2u;
    return sw128(byte);
}
__device__ __forceinline__ void split_f8(const float* f, uint4& hi, uint4& lo) {
    uint32_t hh[4], ll[4];
    #pragma unroll
    for (int q = 0; q < 4; q++) {
        float a0 = f[2*q], a1 = f[2*q+1];
        __nv_bfloat162 h2 = __floats2bfloat162_rn(a0, a1);
        float h0 = __low2float(h2), h1 = __high2float(h2);
        __nv_bfloat162 l2 = __floats2bfloat162_rn(a0 - h0, a1 - h1);
        hh[q] = bf2u(h2); ll[q] = bf2u(l2);
    }
    hi = make_uint4(hh[0], hh[1], hh[2], hh[3]);
    lo = make_uint4(ll[0], ll[1], ll[2], ll[3]);
}
__device__ __forceinline__ void split8(const uint32_t* v, uint4& hi, uint4& lo) {
    float f[8];
    #pragma unroll
    for (int j = 0; j < 8; j++) f[j] = __uint_as_float(v[j]);
    split_f8(f, hi, lo);
}
#endif // TC_PATH

// ---------------------------------------------------------------------------
// Baseline fp32 projection (only does work when TC path is unavailable).
// ---------------------------------------------------------------------------
__global__ __launch_bounds__(256) void proj_kernel(
    const float* __restrict__ Xq, const float* __restrict__ Xk, const float* __restrict__ Xv,
    const float* __restrict__ Wq, const float* __restrict__ Wk, const float* __restrict__ Wv)
{
#if TC_PATH
    return;
#else
    __shared__ float As[32][132];
    __shared__ float Bs[32][132];

    const float* X; const float* W;
    if (blockIdx.z == 0)      { X = Xq; W = Wq; }
    else if (blockIdx.z == 1) { X = Xk; W = Wk; }
    else                      { X = Xv; W = Wv; }

    const int tid  = threadIdx.x;
    const int tx   = tid & 15, ty = tid >> 4;
    const int row0 = blockIdx.x * 128;
    const int n0   = blockIdx.y * 128;

    float acc[8][8];
    #pragma unroll
    for (int i = 0; i < 8; i++)
        #pragma unroll
        for (int j = 0; j < 8; j++) acc[i][j] = 0.f;

    for (int k0 = 0; k0 < 256; k0 += 32) {
        #pragma unroll
        for (int t = 0; t < 4; t++) {
            int idx = tid + t*256;
            int r   = idx >> 3;
            int kq  = idx & 7;
            float4 v = *(const float4*)&X[(size_t)(row0 + r)*256 + k0 + kq*4];
            As[kq*4+0][r] = v.x; As[kq*4+1][r] = v.y;
            As[kq*4+2][r] = v.z; As[kq*4+3][r] = v.w;
        }
        #pragma unroll
        for (int t = 0; t < 4; t++) {
            int kd = t*8 + (tid >> 5);
            int ng = tid & 31;
            int n  = n0 + ng*4;
            int h  = n >> 5, kk = n & 31;
            float4 v = *(const float4*)&W[(size_t)h*8192 + (size_t)(k0+kd)*32 + kk];
            *(float4*)&Bs[kd][ng*4] = v;
        }
        __syncthreads();

        #pragma unroll 8
        for (int kk = 0; kk < 32; kk++) {
            float a[8], bv[8];
            *(float4*)&a[0]  = *(float4*)&As[kk][ty*8];
            *(float4*)&a[4]  = *(float4*)&As[kk][ty*8+4];
            *(float4*)&bv[0] = *(float4*)&Bs[kk][tx*8];
            *(float4*)&bv[4] = *(float4*)&Bs[kk][tx*8+4];
            #pragma unroll
            for (int i = 0; i < 8; i++)
                #pragma unroll
                for (int j = 0; j < 8; j++)
                    acc[i][j] += a[i]*bv[j];
        }
        __syncthreads();
    }

    const int n = n0 + tx*8;
    const int h = n >> 5, kk = n & 31;
    float* O;
    if (blockIdx.z == 0)      O = g_q;
    else if (blockIdx.z == 1) O = g_k;
    else                      O = g_v;
    #pragma unroll
    for (int i = 0; i < 8; i++) {
        int m = row0 + ty*8 + i;
        int b = m >> 10, s = m & 1023;
        float* op = &O[(((size_t)(b*HH + h))*SS + s)*DKK + kk];
        *(float4*)op       = make_float4(acc[i][0], acc[i][1], acc[i][2], acc[i][3]);
        *(float4*)(op + 4) = make_float4(acc[i][4], acc[i][5], acc[i][6], acc[i][7]);
    }
#endif
}

// ---------------------------------------------------------------------------
// tcgen05 projection (R12, unchanged): pipelined chunks, register staging.
// ---------------------------------------------------------------------------
#define PJ_A   0
#define PJ_B   32768
#define PJ_MB  98304
#define PJ_TM  98312
#define SMEM_PJ 98336

__global__ __launch_bounds__(512, 1) void proj2_kernel(
    const float* __restrict__ Xq, const float* __restrict__ Xk, const float* __restrict__ Xv,
    const float* __restrict__ Wq, const float* __restrict__ Wk, const float* __restrict__ Wv)
{
#if TC_PATH
    extern __shared__ char smc[];
    const uint32_t smb = smem_u32(smc);
    const int tid = threadIdx.x, wid = tid >> 5, lane = tid & 31;
    const int z = blockIdx.z;

    const float* X; const float* W;
    if (z == 0)      { X = Xq; W = Wq; }
    else if (z == 1) { X = Xk; W = Wk; }
    else             { X = Xv; W = Wv; }

    const int mtile  = blockIdx.y*128 + blockIdx.x;
    const int sblock = blockIdx.x;
    const int half   = blockIdx.y;

    if (wid == 0) TCGEN05_ALLOC(smb + PJ_TM, 256);
    if (tid == 0) MBARRIER_INIT(smb + PJ_MB, 1);
    __syncthreads();
    uint32_t tmem;
    asm volatile("ld.shared.b32 %0, [%1];" : "=r"(tmem) : "r"(smb + PJ_TM));

    const uint64_t adesc = MAKE_DESC(smb + PJ_A);
    const uint64_t bdesc = MAKE_DESC(smb + PJ_B);
    int cnt = 0;

    int aI0[2], aI1[2];
    int bI0[4], bI1[4];
    #pragma unroll
    for (int t = 0; t < 2; t++) {
        int idx = tid + t*512;
        if (z < 2) { aI0[t] = idx >> 3;  aI1[t] = idx & 7; }
        else       { aI0[t] = idx & 127; aI1[t] = idx >> 7; }
    }
    #pragma unroll
    for (int t = 0; t < 4; t++) {
        int idx = tid + t*512;
        if (z < 2) { bI0[t] = idx & 255; bI1[t] = idx >> 8; }
        else       { bI0[t] = idx >> 3;  bI1[t] = idx & 7; }
    }

    float stA[2][8], stB[4][8];

    auto stage = [&](int ch) {
        const int k0 = ch*64;
        if (z < 2) {
            #pragma unroll
            for (int t = 0; t < 2; t++) {
                const float* xp = X + (size_t)(mtile*128 + aI0[t])*256 + k0 + aI1[t]*8;
                *(float4*)&stA[t][0] = *(const float4*)xp;
                *(float4*)&stA[t][4] = *(const float4*)(xp + 4);
            }
            #pragma unroll
            for (int t = 0; t < 4; t++) {
                int n = bI0[t], hh = n >> 5, kk = n & 31;
                const float* wp = W + (size_t)hh*8192 + (size_t)(k0 + bI1[t]*8)*32 + kk;
                #pragma unroll
                for (int j = 0; j < 8; j++) stB[t][j] = wp[j*32];
            }
        } else {
            #pragma unroll
            for (int t = 0; t < 2; t++) {
                int n = half*128 + aI0[t], hh = n >> 5, kk = n & 31;
                const float* wp = W + (size_t)hh*8192 + (size_t)(k0 + aI1[t]*8)*32 + kk;
                #pragma unroll
                for (int j = 0; j < 8; j++) stA[t][j] = wp[j*32];
            }
            #pragma unroll
            for (int t = 0; t < 4; t++) {
                const float* xp = X + (size_t)(sblock*256 + bI0[t])*256 + k0 + bI1[t]*8;
                *(float4*)&stB[t][0] = *(const float4*)xp;
                *(float4*)&stB[t][4] = *(const float4*)(xp + 4);
            }
        }
    };

    stage(0);

    for (int ch = 0; ch < 4; ch++) {
        if (ch) { MBARRIER_WAIT_PARITY(smb + PJ_MB, cnt & 1); cnt++; TCGEN05_FENCE_AFTER(); }

        #pragma unroll
        for (int t = 0; t < 2; t++) {
            uint4 hi, lo; split_f8(stA[t], hi, lo);
            *(uint4*)(smc + PJ_A + p_off(aI0[t], aI1[t]*8))      = hi;
            *(uint4*)(smc + PJ_A + p_off(aI0[t], 64 + aI1[t]*8)) = lo;
        }
        #pragma unroll
        for (int t = 0; t < 4; t++) {
            uint4 hi, lo; split_f8(stB[t], hi, lo);
            *(uint4*)(smc + PJ_B + b_off(bI0[t], bI1[t]*8))      = hi;
            *(uint4*)(smc + PJ_B + b_off(bI0[t], 64 + bI1[t]*8)) = lo;
        }
        FENCE_ASYNC_SHARED();
        __syncthreads();

        if (wid == 0 && elect_one()) {
            #pragma unroll
            for (int ks = 0; ks < 4; ks++)
                mma_f16_ss(tmem, adesc + 2*ks, bdesc + 2*ks, IDESC_PJ, !(ch == 0 && ks == 0));
            #pragma unroll
            for (int ks = 0; ks < 4; ks++)
                mma_f16_ss(tmem, adesc + 2*ks, bdesc + 2048 + 2*ks, IDESC_PJ, true);
            #pragma unroll
            for (int ks = 0; ks < 4; ks++)
                mma_f16_ss(tmem, adesc + 1024 + 2*ks, bdesc + 2*ks, IDESC_PJ, true);
            TCGEN05_COMMIT(smb + PJ_MB);
        }

        if (ch + 1 < 4) stage(ch + 1);
    }
    MBARRIER_WAIT_PARITY(smb + PJ_MB, cnt & 1); cnt++;
    TCGEN05_FENCE_AFTER();

    const int r  = (wid & 3)*32 + lane;
    const int c0 = (wid >> 2)*64;

    #pragma unroll
    for (int hseg = 0; hseg < 2; hseg++) {
        uint32_t d[32];
        TCGEN05_LD_X32(d, tmem + c0 + hseg*32);
        TCGEN05_WAIT_LD();

        if (z < 2) {
            __nv_bfloat16* O = (z == 0) ? g_Qs : g_Ksx;
            int m = mtile*128 + r, b = m >> 10, s = m & 1023;
            #pragma unroll
            for (int g = 0; g < 4; g++) {
                int n = c0 + hseg*32 + g*8;
                int hh = n >> 5, kk = n & 31;
                uint4 hi, lo; split8(d + g*8, hi, lo);
                __nv_bfloat16* op = O + (((size_t)(b*HH + hh))*SS + s)*64 + kk;
                *(uint4*)op        = hi;
                *(uint4*)(op + 32) = lo;
            }
        } else {
            int n = half*128 + r, hh = n >> 5, kk = n & 31;
            int b = sblock >> 2;
            #pragma unroll
            for (int g = 0; g < 4; g++) {
                int c = c0 + hseg*32 + g*8;
                int s_in = (sblock & 3)*256 + c;
                int tile = s_in >> 7, sl = s_in & 127;
                uint4 hi, lo; split8(d + g*8, hi, lo);
                __nv_bfloat16* vp = g_Vt + (((size_t)(b*HH + hh))*8 + tile)*8192
                                  + (size_t)kk*256 + sl;
                *(uint4*)vp         = hi;
                *(uint4*)(vp + 128) = lo;
            }
        }
    }
    __syncthreads();
    if (wid == 0) TCGEN05_DEALLOC(tmem, 256);
#endif
}

// ---------------------------------------------------------------------------
// Attention, 256 threads, 2 CTAs/SM.  Q lives in TMEM (TS-mode QK).  Single
// K/V/P smem buffers; serialized per-tile schedule (cross-CTA overlap hides
// the waits).  Numerics identical to R9-R12 (shift-40 exp, split-bf16).
// ---------------------------------------------------------------------------
#define SM_K    0        /* [128 x 64 bf16] SW128, 16KB */
#define SM_V    16384    /* [32 x 256 bf16] blocked, 16KB */
#define SM_P    32768    /* [128 x 256 bf16] blocked, 64KB */
#define SM_MSK  98304    /* 1024 floats */
#define SM_RED  102400   /* 2 x 128 floats */
#define SM_LIV  103424   /* 128 floats */
#define SM_MBA  103936
#define SM_MBB  103944
#define SM_TM   103952
#define SMEM_ATTN 103968

__global__ __launch_bounds__(256, 2) void attn_kernel(
    const float* __restrict__ mask, float* __restrict__ out)
{
    extern __shared__ char smc[];
    const int tid  = threadIdx.x;
    const int qb = blockIdx.x, h = blockIdx.y, b = blockIdx.z;

#if TC_PATH
    const uint32_t smb = smem_u32(smc);
    const int wid  = tid >> 5;
    const int lane = tid & 31;
    const int r   = (wid & 3)*32 + lane;    // TMEM lane / query row
    const int ch0 = (wid >> 2)*64;          // my 64-column half

    if (wid == 0) TCGEN05_ALLOC(smb + SM_TM, 256);
    if (tid == 0) { MBARRIER_INIT(smb + SM_MBA, 1); MBARRIER_INIT(smb + SM_MBB, 1); }

    const size_t bh = (size_t)(b*HH + h);
    const __nv_bfloat16* kgb = g_Ksx + bh*(SS*64);
    const __nv_bfloat16* vgb = g_Vt  + bh*(8*32*256);

    // staging slots: 4 uint4 each for K and V
    int kRR[4], kCH[4], vN[4], vC[4];
    #pragma unroll
    for (int s = 0; s < 4; s++) {
        int it = tid + s*256;
        kRR[s] = it >> 3;  kCH[s] = it & 7;
        vN[s]  = it >> 5;  vC[s]  = (it & 31)*8;
    }

    __syncthreads();
    uint32_t tmem;
    asm volatile("ld.shared.b32 %0, [%1];" : "=r"(tmem) : "r"(smb + SM_TM));
    const uint32_t qT = tmem;          // Q: 32 cols
    const uint32_t dO = tmem + 32;     // O: 32 cols
    const uint32_t dS = tmem + 128;    // S: 128 cols

    // ---- prologue ----
    // Q -> TMEM (warps 0-3: row = tid)
    if (tid < 128) {
        const uint4* qp = (const uint4*)(g_Qs + bh*(SS*64) + (size_t)(qb*128 + tid)*64);
        uint32_t q32[32];
        #pragma unroll
        for (int j = 0; j < 8; j++) {
            uint4 v = qp[j];
            q32[j*4+0] = v.x; q32[j*4+1] = v.y; q32[j*4+2] = v.z; q32[j*4+3] = v.w;
        }
        TCGEN05_ST_X32(qT + ((uint32_t)(tid >> 5) << 21), q32);
        TCGEN05_WAIT_ST();
    }
    // mask (256 uint4)
    ((uint4*)(smc + SM_MSK))[tid] = ((const uint4*)(mask + (size_t)b*SS))[tid];
    // K0 / V0
    {
        const uint4* kg = (const uint4*)(kgb);
        const uint4* vg = (const uint4*)(vgb);
        #pragma unroll
        for (int s = 0; s < 4; s++) {
            *(uint4*)(smc + SM_K + sw128(kRR[s]*128 + kCH[s]*16)) = kg[tid + s*256];
            *(uint4*)(smc + SM_V + v_off(vN[s], vC[s]))           = vg[tid + s*256];
        }
    }
    TCGEN05_FENCE_BEFORE();
    FENCE_ASYNC_SHARED();
    __syncthreads();

    const float* Msk = (const float*)(smc + SM_MSK);
    const uint64_t kdesc = MAKE_DESC(smb + SM_K);
    const uint64_t vdesc = MAKE_DESC(smb + SM_V);
    const uint64_t pdesc = MAKE_DESC(smb + SM_P);

    if (wid == 0 && elect_one()) {
        TCGEN05_FENCE_AFTER();
        issue_qk_ts(dS, qT, kdesc, smb + SM_MBA);
    }

    int cntA = 0, cntB = 0;
    float lacc = 0.0f;

    for (int kt = 0; kt < 8; kt++) {
        // stage next K/V tile (LDG latency hidden under QK wait + softmax)
        uint4 kreg[4], vreg[4];
        if (kt + 1 < 8) {
            const uint4* kg = (const uint4*)(kgb + (size_t)(kt + 1)*128*64);
            const uint4* vg = (const uint4*)(vgb + (size_t)(kt + 1)*32*256);
            #pragma unroll
            for (int s = 0; s < 4; s++) { kreg[s] = kg[tid + s*256]; vreg[s] = vg[tid + s*256]; }
        }

        // QK(kt) done -> S valid
        MBARRIER_WAIT_PARITY(smb + SM_MBA, cntA & 1); cntA++;
        TCGEN05_FENCE_AFTER();

        // softmax + split-bf16 P, 4 chunks of 16 columns
        #pragma unroll
        for (int ck = 0; ck < 4; ck++) {
            uint32_t sregs[16];
            TCGEN05_LD_X16(sregs, dS + ch0 + ck*16);
            TCGEN05_WAIT_LD();
            float p[16];
            #pragma unroll
            for (int j = 0; j < 16; j++) {
                float m  = Msk[kt*128 + ch0 + ck*16 + j];
                float sv = fmaf(m, __uint_as_float(sregs[j]), (m - 1.0f)*1e-30f);
                p[j] = __expf(sv - 40.0f);
                lacc += p[j];
            }
            uint4 hi0, lo0, hi1, lo1;
            split_f8(p,     hi0, lo0);
            split_f8(p + 8, hi1, lo1);
            int cb = ch0 + ck*16;
            *(uint4*)(smc + SM_P + p_off(r, cb))           = hi0;
            *(uint4*)(smc + SM_P + p_off(r, cb + 8))       = hi1;
            *(uint4*)(smc + SM_P + p_off(r, 128 + cb))     = lo0;
            *(uint4*)(smc + SM_P + p_off(r, 128 + cb + 8)) = lo1;
        }
        FENCE_ASYNC_SHARED();
        __syncthreads();

        // PV(kt)
        if (wid == 0 && elect_one()) {
            TCGEN05_FENCE_AFTER();
            issue_pv(dO, pdesc, vdesc, kt == 0, smb + SM_MBB);
        }
        // PV(kt) done -> P, V, K free
        MBARRIER_WAIT_PARITY(smb + SM_MBB, cntB & 1); cntB++;

        if (kt + 1 < 8) {
            #pragma unroll
            for (int s = 0; s < 4; s++) {
                *(uint4*)(smc + SM_K + sw128(kRR[s]*128 + kCH[s]*16)) = kreg[s];
                *(uint4*)(smc + SM_V + v_off(vN[s], vC[s]))           = vreg[s];
            }
            FENCE_ASYNC_SHARED();
            __syncthreads();
            if (wid == 0 && elect_one()) {
                TCGEN05_FENCE_AFTER();
                issue_qk_ts(dS, qT, kdesc, smb + SM_MBA);
            }
        }
    }
    TCGEN05_FENCE_AFTER();

    // ---- epilogue ----
    ((float*)(smc + SM_RED))[(wid >> 2)*128 + r] = lacc;
    __syncthreads();
    if (tid < 128) {
        const float* rd = (const float*)(smc + SM_RED);
        ((float*)(smc + SM_LIV))[tid] = 1.0f / (rd[tid] + rd[128 + tid]);
    }
    __syncthreads();

    if (wid < 4) {
        uint32_t oregs[32];
        TCGEN05_LD_X32(oregs, dO);
        TCGEN05_WAIT_LD();
        float inv = ((float*)(smc + SM_LIV))[r];
        float* op = out + (((size_t)b*SS) + qb*128 + r)*256 + h*32;
        #pragma unroll
        for (int g = 0; g < 8; g++) {
            float4 v;
            v.x = __uint_as_float(oregs[g*4+0])*inv;
            v.y = __uint_as_float(oregs[g*4+1])*inv;
            v.z = __uint_as_float(oregs[g*4+2])*inv;
            v.w = __uint_as_float(oregs[g*4+3])*inv;
            *(float4*)(op + g*4) = v;
        }
    }
    __syncthreads();
    if (wid == 0) TCGEN05_DEALLOC(tmem, 256);

#else  // ===================== baseline FFMA flash (256 threads, R1 layout) =====
    float* sm = (float*)smc;
    float* Qt = sm;                        // [32][132]
    float* Kt = Qt + 32*132;               // [32][68]
    float* Vs = Kt + 32*68;                // [64][32]
    float* Ps = Vs + 64*32;                // [128][68]
    float* Ms = Ps + 128*68;               // [64]

    const int tx = tid & 15, ty = tid >> 4;

    const float* qptr = g_q + (((size_t)(b*HH + h))*SS + qb*128)*DKK;
    for (int idx = tid; idx < 128*32; idx += 256) {
        int d = idx & 31, rr = idx >> 5;
        Qt[d*132 + rr] = qptr[idx];
    }

    float m_i[8], l_i[8], o0[8], o1[8];
    #pragma unroll
    for (int i = 0; i < 8; i++) { m_i[i] = -1e38f; l_i[i] = 0.f; o0[i] = 0.f; o1[i] = 0.f; }

    const float* kbase = g_k + ((size_t)(b*HH + h))*SS*DKK;
    const float* vbase = g_v + ((size_t)(b*HH + h))*SS*DKK;
    const float* mbase = mask + (size_t)b*SS;

    for (int kt = 0; kt < 16; kt++) {
        __syncthreads();
        const float* kp = kbase + (size_t)kt*64*32;
        for (int idx = tid; idx < 64*32; idx += 256) {
            int d = idx & 31, rr = idx >> 5;
            Kt[d*68 + rr] = kp[idx];
        }
        const float4* vp = (const float4*)(vbase + (size_t)kt*64*32);
        for (int idx = tid; idx < 64*32/4; idx += 256)
            ((float4*)Vs)[idx] = vp[idx];
        if (tid < 64) Ms[tid] = mbase[kt*64 + tid];
        __syncthreads();

        float sc[8][4];
        #pragma unroll
        for (int i = 0; i < 8; i++)
            #pragma unroll
            for (int j = 0; j < 4; j++) sc[i][j] = 0.f;

        #pragma unroll 8
        for (int d = 0; d < 32; d++) {
            float a[8], kv[4];
            *(float4*)&a[0]  = *(float4*)&Qt[d*132 + ty*8];
            *(float4*)&a[4]  = *(float4*)&Qt[d*132 + ty*8 + 4];
            *(float4*)&kv[0] = *(float4*)&Kt[d*68 + tx*4];
            #pragma unroll
            for (int i = 0; i < 8; i++)
                #pragma unroll
                for (int j = 0; j < 4; j++)
                    sc[i][j] += a[i]*kv[j];
        }

        float mv[4];
        #pragma unroll
        for (int j = 0; j < 4; j++) mv[j] = Ms[tx*4 + j];

        #pragma unroll
        for (int i = 0; i < 8; i++) {
            #pragma unroll
            for (int j = 0; j < 4; j++)
                sc[i][j] = mv[j]*sc[i][j] + (1.f - mv[j])*(-1e-30f);

            float tm = fmaxf(fmaxf(sc[i][0], sc[i][1]), fmaxf(sc[i][2], sc[i][3]));
            #pragma unroll
            for (int off = 8; off > 0; off >>= 1)
                tm = fmaxf(tm, __shfl_xor_sync(0xffffffffu, tm, off));

            float mnew = fmaxf(m_i[i], tm);
            float rs = 0.f;
            #pragma unroll
            for (int j = 0; j < 4; j++) {
                float pp = __expf(sc[i][j] - mnew);
                sc[i][j] = pp;
                rs += pp;
            }
            #pragma unroll
            for (int off = 8; off > 0; off >>= 1)
                rs += __shfl_xor_sync(0xffffffffu, rs, off);

            float alpha = __expf(m_i[i] - mnew);
            l_i[i] = l_i[i]*alpha + rs;
            m_i[i] = mnew;
            o0[i] *= alpha;
            o1[i] *= alpha;

            *(float4*)&Ps[(ty*8+i)*68 + tx*4] =
                make_float4(sc[i][0], sc[i][1], sc[i][2], sc[i][3]);
        }
        __syncthreads();

        #pragma unroll 4
        for (int s0 = 0; s0 < 64; s0 += 4) {
            float2 v0 = *(float2*)&Vs[(s0+0)*32 + tx*2];
            float2 v1 = *(float2*)&Vs[(s0+1)*32 + tx*2];
            float2 v2 = *(float2*)&Vs[(s0+2)*32 + tx*2];
            float2 v3 = *(float2*)&Vs[(s0+3)*32 + tx*2];
            #pragma unroll
            for (int i = 0; i < 8; i++) {
                float4 pp = *(float4*)&Ps[(ty*8+i)*68 + s0];
                o0[i] += pp.x*v0.x + pp.y*v1.x + pp.z*v2.x + pp.w*v3.x;
                o1[i] += pp.x*v0.y + pp.y*v1.y + pp.z*v2.y + pp.w*v3.y;
            }
        }
    }

    #pragma unroll
    for (int i = 0; i < 8; i++) {
        float inv = 1.f / l_i[i];
        int row = qb*128 + ty*8 + i;
        float2 res = make_float2(o0[i]*inv, o1[i]*inv);
        *(float2*)&out[((size_t)b*SS + row)*256 + h*32 + tx*2] = res;
    }
#endif
}

// ---------------------------------------------------------------------------
extern "C" void kernel_launch(void* const* d_in, const int* in_sizes, int n_in,
                              void* d_out, int out_size)
{
    (void)in_sizes; (void)n_in; (void)out_size;
    const float* query = (const float*)d_in[0];
    const float* key   = (const float*)d_in[1];
    const float* value = (const float*)d_in[2];
    const float* mask  = (const float*)d_in[3];
    const float* Wq    = (const float*)d_in[4];
    const float* Wk    = (const float*)d_in[5];
    const float* Wv    = (const float*)d_in[6];
    float* out = (float*)d_out;

    cudaFuncSetAttribute(attn_kernel,
                         cudaFuncAttributeMaxDynamicSharedMemorySize, SMEM_ATTN);
    cudaFuncSetAttribute(proj2_kernel,
                         cudaFuncAttributeMaxDynamicSharedMemorySize, SMEM_PJ);

    proj_kernel<<<dim3(256, 2, 3), 256>>>(query, key, value, Wq, Wk, Wv);
    proj2_kernel<<<dim3(128, 2, 3), 512, SMEM_PJ>>>(query, key, value, Wq, Wk, Wv);
    attn_kernel<<<dim3(8, 8, 32), 256, SMEM_ATTN>>>(mask, out);
}

// round 14
// speedup vs baseline: 1.0331x; 1.0331x over previous
#include <cuda_runtime.h>
#include <cuda_bf16.h>
#include <cstdint>
#include <math.h>

#if defined(__CUDA_ARCH_FEAT_SM103_ALL) || defined(__CUDA_ARCH_FEAT_SM100_ALL)
#define TC_PATH 1
#else
#define TC_PATH 0
#endif

#define BB  32
#define SS  1024
#define DD  256
#define HH  8
#define DKK 32

// ---------------- fp32 scratch (baseline fallback path) ----------------
__device__ float g_q[BB*HH*SS*DKK];
__device__ float g_k[BB*HH*SS*DKK];
__device__ float g_v[BB*HH*SS*DKK];

// ---------------- split-bf16 scratch (tcgen05 path) ----------------
__device__ __nv_bfloat16 g_Qs[BB*HH*SS*64];
__device__ __nv_bfloat16 g_Ksx[BB*HH*SS*64];
__device__ __nv_bfloat16 g_Vt[BB*HH*8*32*256];

// ======================= common helpers =======================
__device__ __forceinline__ uint32_t smem_u32(const void* p) {
    uint32_t a;
    asm("{ .reg .u64 t; cvta.to.shared.u64 t, %1; cvt.u32.u64 %0, t; }" : "=r"(a) : "l"(p));
    return a;
}
__device__ __forceinline__ uint32_t sw128(uint32_t b) { return b ^ ((b >> 3) & 0x70); }
__device__ __forceinline__ uint32_t bf2u(__nv_bfloat162 v) {
    union { __nv_bfloat162 b; uint32_t u; } cv; cv.b = v; return cv.u;
}

#if TC_PATH
// ======================= tcgen05 helpers (sm_103a only) =======================
__device__ __forceinline__ uint32_t elect_one() {
    uint32_t pred;
    asm volatile("{\n\t.reg .pred p;\n\telect.sync _|p, 0xFFFFFFFF;\n\tselp.b32 %0, 1, 0, p;\n\t}" : "=r"(pred));
    return pred;
}
#define TCGEN05_ALLOC(sa, n) \
    asm volatile("tcgen05.alloc.cta_group::1.sync.aligned.shared::cta.b32 [%0], %1;" \
        :: "r"((uint32_t)(sa)), "r"((uint32_t)(n)) : "memory")
#define TCGEN05_DEALLOC(t, n) \
    asm volatile("tcgen05.dealloc.cta_group::1.sync.aligned.b32 %0, %1;" :: "r"(t), "r"((uint32_t)(n)))
#define TCGEN05_COMMIT(mb) \
    asm volatile("tcgen05.commit.cta_group::1.mbarrier::arrive::one.shared::cluster.b64 [%0];" \
        :: "r"((uint32_t)(mb)) : "memory")
#define TCGEN05_WAIT_LD()  asm volatile("tcgen05.wait::ld.sync.aligned;" ::: "memory")
#define TCGEN05_WAIT_ST()  asm volatile("tcgen05.wait::st.sync.aligned;" ::: "memory")
#define TCGEN05_FENCE_AFTER()  asm volatile("tcgen05.fence::after_thread_sync;" ::: "memory")
#define TCGEN05_FENCE_BEFORE() asm volatile("tcgen05.fence::before_thread_sync;" ::: "memory")
#define FENCE_ASYNC_SHARED() asm volatile("fence.proxy.async.shared::cta;" ::: "memory")
#define MBARRIER_INIT(mb, c) \
    asm volatile("mbarrier.init.shared.b64 [%0], %1;" :: "r"((uint32_t)(mb)), "r"((uint32_t)(c)) : "memory")
#define MBARRIER_WAIT_PARITY(mb, ph) do { \
    uint32_t _m = (uint32_t)(mb), _p = (uint32_t)(ph), _d; \
    asm volatile("{\n\t.reg .pred p;\n\t" \
        "mbarrier.try_wait.parity.acquire.cta.shared::cta.b64 p, [%1], %2;\n\t" \
        "selp.b32 %0, 1, 0, p;\n\t}" : "=r"(_d) : "r"(_m), "r"(_p) : "memory"); \
    if (!_d) { \
        asm volatile("{\n\t.reg .pred P1;\n\t" \
            "WL_%=:\n\t" \
            "mbarrier.try_wait.parity.acquire.cta.shared::cta.b64 P1, [%0], %1, 0x989680;\n\t" \
            "@P1 bra.uni WD_%=;\n\tbra.uni WL_%=;\n\tWD_%=:\n\t}" \
            :: "r"(_m), "r"(_p) : "memory"); \
    } } while (0)
#define TCGEN05_LD_X32(r, ta) \
    asm volatile("tcgen05.ld.sync.aligned.32x32b.x32.b32 " \
        "{%0, %1, %2, %3, %4, %5, %6, %7, %8, %9, %10, %11, %12, %13, %14, %15, " \
        " %16, %17, %18, %19, %20, %21, %22, %23, %24, %25, %26, %27, %28, %29, %30, %31}, [%32];" \
        : "=r"((r)[0]),  "=r"((r)[1]),  "=r"((r)[2]),  "=r"((r)[3]), \
          "=r"((r)[4]),  "=r"((r)[5]),  "=r"((r)[6]),  "=r"((r)[7]), \
          "=r"((r)[8]),  "=r"((r)[9]),  "=r"((r)[10]), "=r"((r)[11]), \
          "=r"((r)[12]), "=r"((r)[13]), "=r"((r)[14]), "=r"((r)[15]), \
          "=r"((r)[16]), "=r"((r)[17]), "=r"((r)[18]), "=r"((r)[19]), \
          "=r"((r)[20]), "=r"((r)[21]), "=r"((r)[22]), "=r"((r)[23]), \
          "=r"((r)[24]), "=r"((r)[25]), "=r"((r)[26]), "=r"((r)[27]), \
          "=r"((r)[28]), "=r"((r)[29]), "=r"((r)[30]), "=r"((r)[31]) \
        : "r"(ta))
#define TCGEN05_LD_X16(r, ta) \
    asm volatile("tcgen05.ld.sync.aligned.32x32b.x16.b32 " \
        "{%0, %1, %2, %3, %4, %5, %6, %7, %8, %9, %10, %11, %12, %13, %14, %15}, [%16];" \
        : "=r"((r)[0]),  "=r"((r)[1]),  "=r"((r)[2]),  "=r"((r)[3]), \
          "=r"((r)[4]),  "=r"((r)[5]),  "=r"((r)[6]),  "=r"((r)[7]), \
          "=r"((r)[8]),  "=r"((r)[9]),  "=r"((r)[10]), "=r"((r)[11]), \
          "=r"((r)[12]), "=r"((r)[13]), "=r"((r)[14]), "=r"((r)[15]) \
        : "r"(ta))
#define TCGEN05_ST_X32(ta, r) \
    asm volatile("tcgen05.st.sync.aligned.32x32b.x32.b32 [%0], " \
        "{%1, %2, %3, %4, %5, %6, %7, %8, %9, %10, %11, %12, %13, %14, %15, %16, " \
        " %17, %18, %19, %20, %21, %22, %23, %24, %25, %26, %27, %28, %29, %30, %31, %32};" \
        :: "r"(ta), \
           "r"((r)[0]),  "r"((r)[1]),  "r"((r)[2]),  "r"((r)[3]), \
           "r"((r)[4]),  "r"((r)[5]),  "r"((r)[6]),  "r"((r)[7]), \
           "r"((r)[8]),  "r"((r)[9]),  "r"((r)[10]), "r"((r)[11]), \
           "r"((r)[12]), "r"((r)[13]), "r"((r)[14]), "r"((r)[15]), \
           "r"((r)[16]), "r"((r)[17]), "r"((r)[18]), "r"((r)[19]), \
           "r"((r)[20]), "r"((r)[21]), "r"((r)[22]), "r"((r)[23]), \
           "r"((r)[24]), "r"((r)[25]), "r"((r)[26]), "r"((r)[27]), \
           "r"((r)[28]), "r"((r)[29]), "r"((r)[30]), "r"((r)[31]) \
        : "memory")

static constexpr uint64_t DESC_BASE_SW128 =
    (uint64_t(2) << 61) | (uint64_t(1) << 46) | (uint64_t(64) << 32) | (uint64_t(1) << 16);
#define MAKE_DESC(a) (DESC_BASE_SW128 | ((uint64_t)((a) >> 4) & 0x3FFF))

__device__ __forceinline__ void mma_f16_ss(uint32_t d, uint64_t ad, uint64_t bd,
                                           uint32_t idesc, bool acc) {
    uint32_t en = acc ? 1u : 0u, z = 0u;
    asm volatile(
        "{\n\t.reg .pred p;\n\tsetp.ne.u32 p, %4, 0;\n\t"
        "tcgen05.mma.cta_group::1.kind::f16 [%0], %1, %2, %3, {%5, %5, %5, %5}, p;\n\t}"
        :: "r"(d), "l"(ad), "l"(bd), "r"(idesc), "r"(en), "r"(z) : "memory");
}
__device__ __forceinline__ void mma_f16_ts(uint32_t d, uint32_t a, uint64_t bd,
                                           uint32_t idesc, bool acc) {
    uint32_t en = acc ? 1u : 0u, z = 0u;
    asm volatile(
        "{\n\t.reg .pred p;\n\tsetp.ne.u32 p, %4, 0;\n\t"
        "tcgen05.mma.cta_group::1.kind::f16 [%0], [%1], %2, %3, {%5, %5, %5, %5}, p;\n\t}"
        :: "r"(d), "r"(a), "l"(bd), "r"(idesc), "r"(en), "r"(z) : "memory");
}

// idesc: F32 acc | bf16 A | bf16 B | N | M=128
#define IDESC_QK (0x10u | 0x80u | 0x400u | (16u << 17) | (8u << 24))   /* N=128 */
#define IDESC_PV (0x10u | 0x80u | 0x400u | (4u  << 17) | (8u << 24))   /* N=32  */
#define IDESC_PJ (0x10u | 0x80u | 0x400u | (32u << 17) | (8u << 24))   /* N=256 */

// TS-mode 6-term split-bf16 QK (Q in TMEM: hi @ +0, lo @ +16 cols), commit
__device__ __forceinline__ void issue_qk_ts(uint32_t dS, uint32_t qt, uint64_t kd, uint32_t mb) {
    mma_f16_ts(dS, qt + 0,  kd + 0, IDESC_QK, false);   // hi.hi
    mma_f16_ts(dS, qt + 8,  kd + 2, IDESC_QK, true);
    mma_f16_ts(dS, qt + 0,  kd + 4, IDESC_QK, true);    // hi.lo
    mma_f16_ts(dS, qt + 8,  kd + 6, IDESC_QK, true);
    mma_f16_ts(dS, qt + 16, kd + 0, IDESC_QK, true);    // lo.hi
    mma_f16_ts(dS, qt + 24, kd + 2, IDESC_QK, true);
    TCGEN05_COMMIT(mb);
}
// 24-term split-bf16 PV, then commit
__device__ __forceinline__ void issue_pv(uint32_t dO, uint64_t pd, uint64_t vd,
                                         bool first, uint32_t mb) {
    #pragma unroll
    for (int t = 0; t < 8; t++) {
        uint64_t po = (uint64_t)((t >> 2)*1024 + (t & 3)*2);
        uint64_t vo = (uint64_t)((t >> 2)*256  + (t & 3)*2);
        mma_f16_ss(dO, pd + po, vd + vo, IDESC_PV, !(first && t == 0));
    }
    #pragma unroll
    for (int t = 0; t < 8; t++) {
        uint64_t po = (uint64_t)((t >> 2)*1024 + (t & 3)*2);
        int t2 = t + 8;
        uint64_t vo = (uint64_t)((t2 >> 2)*256 + (t2 & 3)*2);
        mma_f16_ss(dO, pd + po, vd + vo, IDESC_PV, true);
    }
    #pragma unroll
    for (int t = 0; t < 8; t++) {
        int t2 = t + 8;
        uint64_t po = (uint64_t)((t2 >> 2)*1024 + (t2 & 3)*2);
        uint64_t vo = (uint64_t)((t >> 2)*256   + (t & 3)*2);
        mma_f16_ss(dO, pd + po, vd + vo, IDESC_PV, true);
    }
    TCGEN05_COMMIT(mb);
}

__device__ __forceinline__ uint32_t p_off(int r, int c) {
    uint32_t byte = ((uint32_t)(r >> 3) + (uint32_t)(c >> 6)*16u)*1024u
                  + (uint32_t)(r & 7)*128u + (uint32_t)(c & 63)*2u;
    return sw128(byte);
}
__device__ __forceinline__ uint32_t v_off(int n, int c) {
    uint32_t byte = ((uint32_t)(n >> 3) + (uint32_t)(c >> 6)*4u)*1024u
                  + (uint32_t)(n & 7)*128u + (uint32_t)(c & 63)*2u;
    return sw128(byte);
}
__device__ __forceinline__ uint32_t b_off(int n, int c) {
    uint32_t byte = ((uint32_t)(n >> 3) + (uint32_t)(c >> 6)*32u)*1024u
                  + (uint32_t)(n & 7)*128u + (uint32_t)(c & 63)*2u;
    return sw128(byte);
}
__device__ __forceinline__ void split_f8(const float* f, uint4& hi, uint4& lo) {
    uint32_t hh[4], ll[4];
    #pragma unroll
    for (int q = 0; q < 4; q++) {
        float a0 = f[2*q], a1 = f[2*q+1];
        __nv_bfloat162 h2 = __floats2bfloat162_rn(a0, a1);
        float h0 = __low2float(h2), h1 = __high2float(h2);
        __nv_bfloat162 l2 = __floats2bfloat162_rn(a0 - h0, a1 - h1);
        hh[q] = bf2u(h2); ll[q] = bf2u(l2);
    }
    hi = make_uint4(hh[0], hh[1], hh[2], hh[3]);
    lo = make_uint4(ll[0], ll[1], ll[2], ll[3]);
}
__device__ __forceinline__ void split8(const uint32_t* v, uint4& hi, uint4& lo) {
    float f[8];
    #pragma unroll
    for (int j = 0; j < 8; j++) f[j] = __uint_as_float(v[j]);
    split_f8(f, hi, lo);
}
#endif // TC_PATH

// ---------------------------------------------------------------------------
// Baseline fp32 projection (only does work when TC path is unavailable).
// ---------------------------------------------------------------------------
__global__ __launch_bounds__(256) void proj_kernel(
    const float* __restrict__ Xq, const float* __restrict__ Xk, const float* __restrict__ Xv,
    const float* __restrict__ Wq, const float* __restrict__ Wk, const float* __restrict__ Wv)
{
#if TC_PATH
    return;
#else
    __shared__ float As[32][132];
    __shared__ float Bs[32][132];

    const float* X; const float* W;
    if (blockIdx.z == 0)      { X = Xq; W = Wq; }
    else if (blockIdx.z == 1) { X = Xk; W = Wk; }
    else                      { X = Xv; W = Wv; }

    const int tid  = threadIdx.x;
    const int tx   = tid & 15, ty = tid >> 4;
    const int row0 = blockIdx.x * 128;
    const int n0   = blockIdx.y * 128;

    float acc[8][8];
    #pragma unroll
    for (int i = 0; i < 8; i++)
        #pragma unroll
        for (int j = 0; j < 8; j++) acc[i][j] = 0.f;

    for (int k0 = 0; k0 < 256; k0 += 32) {
        #pragma unroll
        for (int t = 0; t < 4; t++) {
            int idx = tid + t*256;
            int r   = idx >> 3;
            int kq  = idx & 7;
            float4 v = *(const float4*)&X[(size_t)(row0 + r)*256 + k0 + kq*4];
            As[kq*4+0][r] = v.x; As[kq*4+1][r] = v.y;
            As[kq*4+2][r] = v.z; As[kq*4+3][r] = v.w;
        }
        #pragma unroll
        for (int t = 0; t < 4; t++) {
            int kd = t*8 + (tid >> 5);
            int ng = tid & 31;
            int n  = n0 + ng*4;
            int h  = n >> 5, kk = n & 31;
            float4 v = *(const float4*)&W[(size_t)h*8192 + (size_t)(k0+kd)*32 + kk];
            *(float4*)&Bs[kd][ng*4] = v;
        }
        __syncthreads();

        #pragma unroll 8
        for (int kk = 0; kk < 32; kk++) {
            float a[8], bv[8];
            *(float4*)&a[0]  = *(float4*)&As[kk][ty*8];
            *(float4*)&a[4]  = *(float4*)&As[kk][ty*8+4];
            *(float4*)&bv[0] = *(float4*)&Bs[kk][tx*8];
            *(float4*)&bv[4] = *(float4*)&Bs[kk][tx*8+4];
            #pragma unroll
            for (int i = 0; i < 8; i++)
                #pragma unroll
                for (int j = 0; j < 8; j++)
                    acc[i][j] += a[i]*bv[j];
        }
        __syncthreads();
    }

    const int n = n0 + tx*8;
    const int h = n >> 5, kk = n & 31;
    float* O;
    if (blockIdx.z == 0)      O = g_q;
    else if (blockIdx.z == 1) O = g_k;
    else                      O = g_v;
    #pragma unroll
    for (int i = 0; i < 8; i++) {
        int m = row0 + ty*8 + i;
        int b = m >> 10, s = m & 1023;
        float* op = &O[(((size_t)(b*HH + h))*SS + s)*DKK + kk];
        *(float4*)op       = make_float4(acc[i][0], acc[i][1], acc[i][2], acc[i][3]);
        *(float4*)(op + 4) = make_float4(acc[i][4], acc[i][5], acc[i][6], acc[i][7]);
    }
#endif
}

// ---------------------------------------------------------------------------
// tcgen05 projection (R12, unchanged): pipelined chunks, register staging.
// ---------------------------------------------------------------------------
#define PJ_A   0
#define PJ_B   32768
#define PJ_MB  98304
#define PJ_TM  98312
#define SMEM_PJ 98336

__global__ __launch_bounds__(512, 1) void proj2_kernel(
    const float* __restrict__ Xq, const float* __restrict__ Xk, const float* __restrict__ Xv,
    const float* __restrict__ Wq, const float* __restrict__ Wk, const float* __restrict__ Wv)
{
#if TC_PATH
    extern __shared__ char smc[];
    const uint32_t smb = smem_u32(smc);
    const int tid = threadIdx.x, wid = tid >> 5, lane = tid & 31;
    const int z = blockIdx.z;

    const float* X; const float* W;
    if (z == 0)      { X = Xq; W = Wq; }
    else if (z == 1) { X = Xk; W = Wk; }
    else             { X = Xv; W = Wv; }

    const int mtile  = blockIdx.y*128 + blockIdx.x;
    const int sblock = blockIdx.x;
    const int half   = blockIdx.y;

    if (wid == 0) TCGEN05_ALLOC(smb + PJ_TM, 256);
    if (tid == 0) MBARRIER_INIT(smb + PJ_MB, 1);
    __syncthreads();
    uint32_t tmem;
    asm volatile("ld.shared.b32 %0, [%1];" : "=r"(tmem) : "r"(smb + PJ_TM));

    const uint64_t adesc = MAKE_DESC(smb + PJ_A);
    const uint64_t bdesc = MAKE_DESC(smb + PJ_B);
    int cnt = 0;

    int aI0[2], aI1[2];
    int bI0[4], bI1[4];
    #pragma unroll
    for (int t = 0; t < 2; t++) {
        int idx = tid + t*512;
        if (z < 2) { aI0[t] = idx >> 3;  aI1[t] = idx & 7; }
        else       { aI0[t] = idx & 127; aI1[t] = idx >> 7; }
    }
    #pragma unroll
    for (int t = 0; t < 4; t++) {
        int idx = tid + t*512;
        if (z < 2) { bI0[t] = idx & 255; bI1[t] = idx >> 8; }
        else       { bI0[t] = idx >> 3;  bI1[t] = idx & 7; }
    }

    float stA[2][8], stB[4][8];

    auto stage = [&](int ch) {
        const int k0 = ch*64;
        if (z < 2) {
            #pragma unroll
            for (int t = 0; t < 2; t++) {
                const float* xp = X + (size_t)(mtile*128 + aI0[t])*256 + k0 + aI1[t]*8;
                *(float4*)&stA[t][0] = *(const float4*)xp;
                *(float4*)&stA[t][4] = *(const float4*)(xp + 4);
            }
            #pragma unroll
            for (int t = 0; t < 4; t++) {
                int n = bI0[t], hh = n >> 5, kk = n & 31;
                const float* wp = W + (size_t)hh*8192 + (size_t)(k0 + bI1[t]*8)*32 + kk;
                #pragma unroll
                for (int j = 0; j < 8; j++) stB[t][j] = wp[j*32];
            }
        } else {
            #pragma unroll
            for (int t = 0; t < 2; t++) {
                int n = half*128 + aI0[t], hh = n >> 5, kk = n & 31;
                const float* wp = W + (size_t)hh*8192 + (size_t)(k0 + aI1[t]*8)*32 + kk;
                #pragma unroll
                for (int j = 0; j < 8; j++) stA[t][j] = wp[j*32];
            }
            #pragma unroll
            for (int t = 0; t < 4; t++) {
                const float* xp = X + (size_t)(sblock*256 + bI0[t])*256 + k0 + bI1[t]*8;
                *(float4*)&stB[t][0] = *(const float4*)xp;
                *(float4*)&stB[t][4] = *(const float4*)(xp + 4);
            }
        }
    };

    stage(0);

    for (int ch = 0; ch < 4; ch++) {
        if (ch) { MBARRIER_WAIT_PARITY(smb + PJ_MB, cnt & 1); cnt++; TCGEN05_FENCE_AFTER(); }

        #pragma unroll
        for (int t = 0; t < 2; t++) {
            uint4 hi, lo; split_f8(stA[t], hi, lo);
            *(uint4*)(smc + PJ_A + p_off(aI0[t], aI1[t]*8))      = hi;
            *(uint4*)(smc + PJ_A + p_off(aI0[t], 64 + aI1[t]*8)) = lo;
        }
        #pragma unroll
        for (int t = 0; t < 4; t++) {
            uint4 hi, lo; split_f8(stB[t], hi, lo);
            *(uint4*)(smc + PJ_B + b_off(bI0[t], bI1[t]*8))      = hi;
            *(uint4*)(smc + PJ_B + b_off(bI0[t], 64 + bI1[t]*8)) = lo;
        }
        FENCE_ASYNC_SHARED();
        __syncthreads();

        if (wid == 0 && elect_one()) {
            #pragma unroll
            for (int ks = 0; ks < 4; ks++)
                mma_f16_ss(tmem, adesc + 2*ks, bdesc + 2*ks, IDESC_PJ, !(ch == 0 && ks == 0));
            #pragma unroll
            for (int ks = 0; ks < 4; ks++)
                mma_f16_ss(tmem, adesc + 2*ks, bdesc + 2048 + 2*ks, IDESC_PJ, true);
            #pragma unroll
            for (int ks = 0; ks < 4; ks++)
                mma_f16_ss(tmem, adesc + 1024 + 2*ks, bdesc + 2*ks, IDESC_PJ, true);
            TCGEN05_COMMIT(smb + PJ_MB);
        }

        if (ch + 1 < 4) stage(ch + 1);
    }
    MBARRIER_WAIT_PARITY(smb + PJ_MB, cnt & 1); cnt++;
    TCGEN05_FENCE_AFTER();

    const int r  = (wid & 3)*32 + lane;
    const int c0 = (wid >> 2)*64;

    #pragma unroll
    for (int hseg = 0; hseg < 2; hseg++) {
        uint32_t d[32];
        TCGEN05_LD_X32(d, tmem + c0 + hseg*32);
        TCGEN05_WAIT_LD();

        if (z < 2) {
            __nv_bfloat16* O = (z == 0) ? g_Qs : g_Ksx;
            int m = mtile*128 + r, b = m >> 10, s = m & 1023;
            #pragma unroll
            for (int g = 0; g < 4; g++) {
                int n = c0 + hseg*32 + g*8;
                int hh = n >> 5, kk = n & 31;
                uint4 hi, lo; split8(d + g*8, hi, lo);
                __nv_bfloat16* op = O + (((size_t)(b*HH + hh))*SS + s)*64 + kk;
                *(uint4*)op        = hi;
                *(uint4*)(op + 32) = lo;
            }
        } else {
            int n = half*128 + r, hh = n >> 5, kk = n & 31;
            int b = sblock >> 2;
            #pragma unroll
            for (int g = 0; g < 4; g++) {
                int c = c0 + hseg*32 + g*8;
                int s_in = (sblock & 3)*256 + c;
                int tile = s_in >> 7, sl = s_in & 127;
                uint4 hi, lo; split8(d + g*8, hi, lo);
                __nv_bfloat16* vp = g_Vt + (((size_t)(b*HH + hh))*8 + tile)*8192
                                  + (size_t)kk*256 + sl;
                *(uint4*)vp         = hi;
                *(uint4*)(vp + 128) = lo;
            }
        }
    }
    __syncthreads();
    if (wid == 0) TCGEN05_DEALLOC(tmem, 256);
#endif
}

// ---------------------------------------------------------------------------
// Attention, 256 threads, 2 CTAs/SM, DEFERRED waits (fix of R13):
//   - MBB(kt-1) wait immediately after MBA(kt) wait (PV finishes before QK).
//   - PV(kt) + QK(kt+1) issued after the single per-tile sync; waited next iter
//     -> PV/QK overlap the next tile's staging, K/V STS, LDTM and exp.
//   - Q in TMEM (TS-mode QK, validated in R13); single S buffer (safe: all
//     LDTM complete before the sync that precedes QK(kt+1)'s commit).
//   - V single-buffered with one-iteration register carry.
// ---------------------------------------------------------------------------
#define SM_K    0        /* [128 x 64 bf16] SW128, 16KB */
#define SM_V    16384    /* [32 x 256 bf16] blocked, 16KB */
#define SM_P    32768    /* [128 x 256 bf16] blocked, 64KB */
#define SM_MSK  98304    /* 1024 floats */
#define SM_RED  102400   /* 2 x 128 floats */
#define SM_LIV  103424   /* 128 floats */
#define SM_MBA  103936
#define SM_MBB  103944
#define SM_TM   103952
#define SMEM_ATTN 103968

__global__ __launch_bounds__(256, 2) void attn_kernel(
    const float* __restrict__ mask, float* __restrict__ out)
{
    extern __shared__ char smc[];
    const int tid  = threadIdx.x;
    const int qb = blockIdx.x, h = blockIdx.y, b = blockIdx.z;

#if TC_PATH
    const uint32_t smb = smem_u32(smc);
    const int wid  = tid >> 5;
    const int lane = tid & 31;
    const int r   = (wid & 3)*32 + lane;    // TMEM lane / query row
    const int ch0 = (wid >> 2)*64;          // my 64-column half

    if (wid == 0) TCGEN05_ALLOC(smb + SM_TM, 256);
    if (tid == 0) { MBARRIER_INIT(smb + SM_MBA, 1); MBARRIER_INIT(smb + SM_MBB, 1); }

    const size_t bh = (size_t)(b*HH + h);
    const __nv_bfloat16* kgb = g_Ksx + bh*(SS*64);
    const __nv_bfloat16* vgb = g_Vt  + bh*(8*32*256);

    // staging slots: 4 uint4 each for K and V
    int kRR[4], kCH[4], vN[4], vC[4];
    #pragma unroll
    for (int s = 0; s < 4; s++) {
        int it = tid + s*256;
        kRR[s] = it >> 3;  kCH[s] = it & 7;
        vN[s]  = it >> 5;  vC[s]  = (it & 31)*8;
    }

    __syncthreads();
    uint32_t tmem;
    asm volatile("ld.shared.b32 %0, [%1];" : "=r"(tmem) : "r"(smb + SM_TM));
    const uint32_t qT = tmem;          // Q: 32 cols
    const uint32_t dO = tmem + 32;     // O: 32 cols
    const uint32_t dS = tmem + 128;    // S: 128 cols

    // ---- prologue ----
    if (tid < 128) {   // Q -> TMEM
        const uint4* qp = (const uint4*)(g_Qs + bh*(SS*64) + (size_t)(qb*128 + tid)*64);
        uint32_t q32[32];
        #pragma unroll
        for (int j = 0; j < 8; j++) {
            uint4 v = qp[j];
            q32[j*4+0] = v.x; q32[j*4+1] = v.y; q32[j*4+2] = v.z; q32[j*4+3] = v.w;
        }
        TCGEN05_ST_X32(qT + ((uint32_t)(tid >> 5) << 21), q32);
        TCGEN05_WAIT_ST();
    }
    ((uint4*)(smc + SM_MSK))[tid] = ((const uint4*)(mask + (size_t)b*SS))[tid];
    {
        const uint4* kg = (const uint4*)(kgb);
        const uint4* vg = (const uint4*)(vgb);
        #pragma unroll
        for (int s = 0; s < 4; s++) {
            *(uint4*)(smc + SM_K + sw128(kRR[s]*128 + kCH[s]*16)) = kg[tid + s*256];
            *(uint4*)(smc + SM_V + v_off(vN[s], vC[s]))           = vg[tid + s*256];
        }
    }
    TCGEN05_FENCE_BEFORE();
    FENCE_ASYNC_SHARED();
    __syncthreads();

    const float* Msk = (const float*)(smc + SM_MSK);
    const uint64_t kdesc = MAKE_DESC(smb + SM_K);
    const uint64_t vdesc = MAKE_DESC(smb + SM_V);
    const uint64_t pdesc = MAKE_DESC(smb + SM_P);

    if (wid == 0 && elect_one()) {
        TCGEN05_FENCE_AFTER();
        issue_qk_ts(dS, qT, kdesc, smb + SM_MBA);
    }

    int cntA = 0, cntB = 0;
    float lacc = 0.0f;
    uint4 vprev[4];   // V tile staged last iteration, stored this iteration

    for (int kt = 0; kt < 8; kt++) {
        // 1. stage K(kt+1)/V(kt+1) (LDG hidden under MBA/MBB waits + softmax)
        uint4 kreg[4], vreg[4];
        if (kt + 1 < 8) {
            const uint4* kg = (const uint4*)(kgb + (size_t)(kt + 1)*128*64);
            const uint4* vg = (const uint4*)(vgb + (size_t)(kt + 1)*32*256);
            #pragma unroll
            for (int s = 0; s < 4; s++) { kreg[s] = kg[tid + s*256]; vreg[s] = vg[tid + s*256]; }
        }

        // 2. QK(kt) done -> S valid, K free
        MBARRIER_WAIT_PARITY(smb + SM_MBA, cntA & 1); cntA++;
        // 3. PV(kt-1) done -> P free, V free
        if (kt) { MBARRIER_WAIT_PARITY(smb + SM_MBB, cntB & 1); cntB++; }
        TCGEN05_FENCE_AFTER();

        // 4. refill K with tile kt+1; refill V with tile kt (staged last iter)
        if (kt + 1 < 8) {
            #pragma unroll
            for (int s = 0; s < 4; s++)
                *(uint4*)(smc + SM_K + sw128(kRR[s]*128 + kCH[s]*16)) = kreg[s];
        }
        if (kt) {
            #pragma unroll
            for (int s = 0; s < 4; s++)
                *(uint4*)(smc + SM_V + v_off(vN[s], vC[s])) = vprev[s];
        }

        // 5. softmax + split-bf16 P (4 chunks of 16 columns)
        #pragma unroll
        for (int ck = 0; ck < 4; ck++) {
            uint32_t sregs[16];
            TCGEN05_LD_X16(sregs, dS + ch0 + ck*16);
            TCGEN05_WAIT_LD();
            float p[16];
            #pragma unroll
            for (int j = 0; j < 16; j++) {
                float m  = Msk[kt*128 + ch0 + ck*16 + j];
                float sv = fmaf(m, __uint_as_float(sregs[j]), (m - 1.0f)*1e-30f);
                p[j] = __expf(sv - 40.0f);
                lacc += p[j];
            }
            uint4 hi0, lo0, hi1, lo1;
            split_f8(p,     hi0, lo0);
            split_f8(p + 8, hi1, lo1);
            int cb = ch0 + ck*16;
            *(uint4*)(smc + SM_P + p_off(r, cb))           = hi0;
            *(uint4*)(smc + SM_P + p_off(r, cb + 8))       = hi1;
            *(uint4*)(smc + SM_P + p_off(r, 128 + cb))     = lo0;
            *(uint4*)(smc + SM_P + p_off(r, 128 + cb + 8)) = lo1;
        }

        // 6. single sync: smem K/V/P ready, all warps past LDTM and both waits
        FENCE_ASYNC_SHARED();
        __syncthreads();

        // 7. issue QK(kt+1) (new K) and PV(kt) (current V); wait next iter
        if (wid == 0 && elect_one()) {
            TCGEN05_FENCE_AFTER();
            if (kt + 1 < 8)
                issue_qk_ts(dS, qT, kdesc, smb + SM_MBA);
            issue_pv(dO, pdesc, vdesc, kt == 0, smb + SM_MBB);
        }
        #pragma unroll
        for (int s = 0; s < 4; s++) vprev[s] = vreg[s];
    }
    MBARRIER_WAIT_PARITY(smb + SM_MBB, cntB & 1); cntB++;
    TCGEN05_FENCE_AFTER();

    // ---- epilogue ----
    ((float*)(smc + SM_RED))[(wid >> 2)*128 + r] = lacc;
    __syncthreads();
    if (tid < 128) {
        const float* rd = (const float*)(smc + SM_RED);
        ((float*)(smc + SM_LIV))[tid] = 1.0f / (rd[tid] + rd[128 + tid]);
    }
    __syncthreads();

    if (wid < 4) {
        uint32_t oregs[32];
        TCGEN05_LD_X32(oregs, dO);
        TCGEN05_WAIT_LD();
        float inv = ((float*)(smc + SM_LIV))[r];
        float* op = out + (((size_t)b*SS) + qb*128 + r)*256 + h*32;
        #pragma unroll
        for (int g = 0; g < 8; g++) {
            float4 v;
            v.x = __uint_as_float(oregs[g*4+0])*inv;
            v.y = __uint_as_float(oregs[g*4+1])*inv;
            v.z = __uint_as_float(oregs[g*4+2])*inv;
            v.w = __uint_as_float(oregs[g*4+3])*inv;
            *(float4*)(op + g*4) = v;
        }
    }
    __syncthreads();
    if (wid == 0) TCGEN05_DEALLOC(tmem, 256);

#else  // ===================== baseline FFMA flash (256 threads) =====
    float* sm = (float*)smc;
    float* Qt = sm;
    float* Kt = Qt + 32*132;
    float* Vs = Kt + 32*68;
    float* Ps = Vs + 64*32;
    float* Ms = Ps + 128*68;

    const int tx = tid & 15, ty = tid >> 4;

    const float* qptr = g_q + (((size_t)(b*HH + h))*SS + qb*128)*DKK;
    for (int idx = tid; idx < 128*32; idx += 256) {
        int d = idx & 31, rr = idx >> 5;
        Qt[d*132 + rr] = qptr[idx];
    }

    float m_i[8], l_i[8], o0[8], o1[8];
    #pragma unroll
    for (int i = 0; i < 8; i++) { m_i[i] = -1e38f; l_i[i] = 0.f; o0[i] = 0.f; o1[i] = 0.f; }

    const float* kbase = g_k + ((size_t)(b*HH + h))*SS*DKK;
    const float* vbase = g_v + ((size_t)(b*HH + h))*SS*DKK;
    const float* mbase = mask + (size_t)b*SS;

    for (int kt = 0; kt < 16; kt++) {
        __syncthreads();
        const float* kp = kbase + (size_t)kt*64*32;
        for (int idx = tid; idx < 64*32; idx += 256) {
            int d = idx & 31, rr = idx >> 5;
            Kt[d*68 + rr] = kp[idx];
        }
        const float4* vp = (const float4*)(vbase + (size_t)kt*64*32);
        for (int idx = tid; idx < 64*32/4; idx += 256)
            ((float4*)Vs)[idx] = vp[idx];
        if (tid < 64) Ms[tid] = mbase[kt*64 + tid];
        __syncthreads();

        float sc[8][4];
        #pragma unroll
        for (int i = 0; i < 8; i++)
            #pragma unroll
            for (int j = 0; j < 4; j++) sc[i][j] = 0.f;

        #pragma unroll 8
        for (int d = 0; d < 32; d++) {
            float a[8], kv[4];
            *(float4*)&a[0]  = *(float4*)&Qt[d*132 + ty*8];
            *(float4*)&a[4]  = *(float4*)&Qt[d*132 + ty*8 + 4];
            *(float4*)&kv[0] = *(float4*)&Kt[d*68 + tx*4];
            #pragma unroll
            for (int i = 0; i < 8; i++)
                #pragma unroll
                for (int j = 0; j < 4; j++)
                    sc[i][j] += a[i]*kv[j];
        }

        float mv[4];
        #pragma unroll
        for (int j = 0; j < 4; j++) mv[j] = Ms[tx*4 + j];

        #pragma unroll
        for (int i = 0; i < 8; i++) {
            #pragma unroll
            for (int j = 0; j < 4; j++)
                sc[i][j] = mv[j]*sc[i][j] + (1.f - mv[j])*(-1e-30f);

            float tm = fmaxf(fmaxf(sc[i][0], sc[i][1]), fmaxf(sc[i][2], sc[i][3]));
            #pragma unroll
            for (int off = 8; off > 0; off >>= 1)
                tm = fmaxf(tm, __shfl_xor_sync(0xffffffffu, tm, off));

            float mnew = fmaxf(m_i[i], tm);
            float rs = 0.f;
            #pragma unroll
            for (int j = 0; j < 4; j++) {
                float pp = __expf(sc[i][j] - mnew);
                sc[i][j] = pp;
                rs += pp;
            }
            #pragma unroll
            for (int off = 8; off > 0; off >>= 1)
                rs += __shfl_xor_sync(0xffffffffu, rs, off);

            float alpha = __expf(m_i[i] - mnew);
            l_i[i] = l_i[i]*alpha + rs;
            m_i[i] = mnew;
            o0[i] *= alpha;
            o1[i] *= alpha;

            *(float4*)&Ps[(ty*8+i)*68 + tx*4] =
                make_float4(sc[i][0], sc[i][1], sc[i][2], sc[i][3]);
        }
        __syncthreads();

        #pragma unroll 4
        for (int s0 = 0; s0 < 64; s0 += 4) {
            float2 v0 = *(float2*)&Vs[(s0+0)*32 + tx*2];
            float2 v1 = *(float2*)&Vs[(s0+1)*32 + tx*2];
            float2 v2 = *(float2*)&Vs[(s0+2)*32 + tx*2];
            float2 v3 = *(float2*)&Vs[(s0+3)*32 + tx*2];
            #pragma unroll
            for (int i = 0; i < 8; i++) {
                float4 pp = *(float4*)&Ps[(ty*8+i)*68 + s0];
                o0[i] += pp.x*v0.x + pp.y*v1.x + pp.z*v2.x + pp.w*v3.x;
                o1[i] += pp.x*v0.y + pp.y*v1.y + pp.z*v2.y + pp.w*v3.y;
            }
        }
    }

    #pragma unroll
    for (int i = 0; i < 8; i++) {
        float inv = 1.f / l_i[i];
        int row = qb*128 + ty*8 + i;
        float2 res = make_float2(o0[i]*inv, o1[i]*inv);
        *(float2*)&out[((size_t)b*SS + row)*256 + h*32 + tx*2] = res;
    }
#endif
}

// ---------------------------------------------------------------------------
extern "C" void kernel_launch(void* const* d_in, const int* in_sizes, int n_in,
                              void* d_out, int out_size)
{
    (void)in_sizes; (void)n_in; (void)out_size;
    const float* query = (const float*)d_in[0];
    const float* key   = (const float*)d_in[1];
    const float* value = (const float*)d_in[2];
    const float* mask  = (const float*)d_in[3];
    const float* Wq    = (const float*)d_in[4];
    const float* Wk    = (const float*)d_in[5];
    const float* Wv    = (const float*)d_in[6];
    float* out = (float*)d_out;

    cudaFuncSetAttribute(attn_kernel,
                         cudaFuncAttributeMaxDynamicSharedMemorySize, SMEM_ATTN);
    cudaFuncSetAttribute(proj2_kernel,
                         cudaFuncAttributeMaxDynamicSharedMemorySize, SMEM_PJ);

    proj_kernel<<<dim3(256, 2, 3), 256>>>(query, key, value, Wq, Wk, Wv);
    proj2_kernel<<<dim3(128, 2, 3), 512, SMEM_PJ>>>(query, key, value, Wq, Wk, Wv);
    attn_kernel<<<dim3(8, 8, 32), 256, SMEM_ATTN>>>(mask, out);
}

// round 15
// speedup vs baseline: 1.0379x; 1.0047x over previous
#include <cuda_runtime.h>
#include <cuda_bf16.h>
#include <cstdint>
#include <math.h>

#if defined(__CUDA_ARCH_FEAT_SM103_ALL) || defined(__CUDA_ARCH_FEAT_SM100_ALL)
#define TC_PATH 1
#else
#define TC_PATH 0
#endif

#define BB  32
#define SS  1024
#define DD  256
#define HH  8
#define DKK 32

// ---------------- fp32 scratch (baseline fallback path) ----------------
__device__ float g_q[BB*HH*SS*DKK];
__device__ float g_k[BB*HH*SS*DKK];
__device__ float g_v[BB*HH*SS*DKK];

// ---------------- split-bf16 scratch (tcgen05 path) ----------------
__device__ __nv_bfloat16 g_Qs[BB*HH*SS*64];
__device__ __nv_bfloat16 g_Ksx[BB*HH*SS*64];
__device__ __nv_bfloat16 g_Vt[BB*HH*8*32*256];

// ======================= common helpers =======================
__device__ __forceinline__ uint32_t smem_u32(const void* p) {
    uint32_t a;
    asm("{ .reg .u64 t; cvta.to.shared.u64 t, %1; cvt.u32.u64 %0, t; }" : "=r"(a) : "l"(p));
    return a;
}
__device__ __forceinline__ uint32_t sw128(uint32_t b) { return b ^ ((b >> 3) & 0x70); }
__device__ __forceinline__ uint32_t bf2u(__nv_bfloat162 v) {
    union { __nv_bfloat162 b; uint32_t u; } cv; cv.b = v; return cv.u;
}

#if TC_PATH
// ======================= tcgen05 helpers (sm_103a only) =======================
__device__ __forceinline__ uint32_t elect_one() {
    uint32_t pred;
    asm volatile("{\n\t.reg .pred p;\n\telect.sync _|p, 0xFFFFFFFF;\n\tselp.b32 %0, 1, 0, p;\n\t}" : "=r"(pred));
    return pred;
}
#define TCGEN05_ALLOC(sa, n) \
    asm volatile("tcgen05.alloc.cta_group::1.sync.aligned.shared::cta.b32 [%0], %1;" \
        :: "r"((uint32_t)(sa)), "r"((uint32_t)(n)) : "memory")
#define TCGEN05_DEALLOC(t, n) \
    asm volatile("tcgen05.dealloc.cta_group::1.sync.aligned.b32 %0, %1;" :: "r"(t), "r"((uint32_t)(n)))
#define TCGEN05_COMMIT(mb) \
    asm volatile("tcgen05.commit.cta_group::1.mbarrier::arrive::one.shared::cluster.b64 [%0];" \
        :: "r"((uint32_t)(mb)) : "memory")
#define TCGEN05_WAIT_LD()  asm volatile("tcgen05.wait::ld.sync.aligned;" ::: "memory")
#define TCGEN05_FENCE_AFTER()  asm volatile("tcgen05.fence::after_thread_sync;" ::: "memory")
#define FENCE_ASYNC_SHARED() asm volatile("fence.proxy.async.shared::cta;" ::: "memory")
#define MBARRIER_INIT(mb, c) \
    asm volatile("mbarrier.init.shared.b64 [%0], %1;" :: "r"((uint32_t)(mb)), "r"((uint32_t)(c)) : "memory")
#define MBARRIER_WAIT_PARITY(mb, ph) do { \
    uint32_t _m = (uint32_t)(mb), _p = (uint32_t)(ph), _d; \
    asm volatile("{\n\t.reg .pred p;\n\t" \
        "mbarrier.try_wait.parity.acquire.cta.shared::cta.b64 p, [%1], %2;\n\t" \
        "selp.b32 %0, 1, 0, p;\n\t}" : "=r"(_d) : "r"(_m), "r"(_p) : "memory"); \
    if (!_d) { \
        asm volatile("{\n\t.reg .pred P1;\n\t" \
            "WL_%=:\n\t" \
            "mbarrier.try_wait.parity.acquire.cta.shared::cta.b64 P1, [%0], %1, 0x989680;\n\t" \
            "@P1 bra.uni WD_%=;\n\tbra.uni WL_%=;\n\tWD_%=:\n\t}" \
            :: "r"(_m), "r"(_p) : "memory"); \
    } } while (0)
#define TCGEN05_LD_X32(r, ta) \
    asm volatile("tcgen05.ld.sync.aligned.32x32b.x32.b32 " \
        "{%0, %1, %2, %3, %4, %5, %6, %7, %8, %9, %10, %11, %12, %13, %14, %15, " \
        " %16, %17, %18, %19, %20, %21, %22, %23, %24, %25, %26, %27, %28, %29, %30, %31}, [%32];" \
        : "=r"((r)[0]),  "=r"((r)[1]),  "=r"((r)[2]),  "=r"((r)[3]), \
          "=r"((r)[4]),  "=r"((r)[5]),  "=r"((r)[6]),  "=r"((r)[7]), \
          "=r"((r)[8]),  "=r"((r)[9]),  "=r"((r)[10]), "=r"((r)[11]), \
          "=r"((r)[12]), "=r"((r)[13]), "=r"((r)[14]), "=r"((r)[15]), \
          "=r"((r)[16]), "=r"((r)[17]), "=r"((r)[18]), "=r"((r)[19]), \
          "=r"((r)[20]), "=r"((r)[21]), "=r"((r)[22]), "=r"((r)[23]), \
          "=r"((r)[24]), "=r"((r)[25]), "=r"((r)[26]), "=r"((r)[27]), \
          "=r"((r)[28]), "=r"((r)[29]), "=r"((r)[30]), "=r"((r)[31]) \
        : "r"(ta))

static constexpr uint64_t DESC_BASE_SW128 =
    (uint64_t(2) << 61) | (uint64_t(1) << 46) | (uint64_t(64) << 32) | (uint64_t(1) << 16);
#define MAKE_DESC(a) (DESC_BASE_SW128 | ((uint64_t)((a) >> 4) & 0x3FFF))

__device__ __forceinline__ void mma_f16_ss(uint32_t d, uint64_t ad, uint64_t bd,
                                           uint32_t idesc, bool acc) {
    uint32_t en = acc ? 1u : 0u, z = 0u;
    asm volatile(
        "{\n\t.reg .pred p;\n\tsetp.ne.u32 p, %4, 0;\n\t"
        "tcgen05.mma.cta_group::1.kind::f16 [%0], %1, %2, %3, {%5, %5, %5, %5}, p;\n\t}"
        :: "r"(d), "l"(ad), "l"(bd), "r"(idesc), "r"(en), "r"(z) : "memory");
}

// idesc: F32 acc | bf16 A | bf16 B | N | M=128
#define IDESC_QK (0x10u | 0x80u | 0x400u | (16u << 17) | (8u << 24))   /* N=128 */
#define IDESC_PV (0x10u | 0x80u | 0x400u | (4u  << 17) | (8u << 24))   /* N=32  */
#define IDESC_PJ (0x10u | 0x80u | 0x400u | (32u << 17) | (8u << 24))   /* N=256 */

// 6-term split-bf16 QK (hi.hi + hi.lo + lo.hi), then commit
__device__ __forceinline__ void issue_qk(uint32_t dS, uint64_t qd, uint64_t kd, uint32_t mb) {
    mma_f16_ss(dS, qd + 0, kd + 0, IDESC_QK, false);
    mma_f16_ss(dS, qd + 2, kd + 2, IDESC_QK, true);
    mma_f16_ss(dS, qd + 0, kd + 4, IDESC_QK, true);
    mma_f16_ss(dS, qd + 2, kd + 6, IDESC_QK, true);
    mma_f16_ss(dS, qd + 4, kd + 0, IDESC_QK, true);
    mma_f16_ss(dS, qd + 6, kd + 2, IDESC_QK, true);
    TCGEN05_COMMIT(mb);
}
// 24-term split-bf16 PV, then commit
__device__ __forceinline__ void issue_pv(uint32_t dO, uint64_t pd, uint64_t vd,
                                         bool first, uint32_t mb) {
    #pragma unroll
    for (int t = 0; t < 8; t++) {
        uint64_t po = (uint64_t)((t >> 2)*1024 + (t & 3)*2);
        uint64_t vo = (uint64_t)((t >> 2)*256  + (t & 3)*2);
        mma_f16_ss(dO, pd + po, vd + vo, IDESC_PV, !(first && t == 0));
    }
    #pragma unroll
    for (int t = 0; t < 8; t++) {
        uint64_t po = (uint64_t)((t >> 2)*1024 + (t & 3)*2);
        int t2 = t + 8;
        uint64_t vo = (uint64_t)((t2 >> 2)*256 + (t2 & 3)*2);
        mma_f16_ss(dO, pd + po, vd + vo, IDESC_PV, true);
    }
    #pragma unroll
    for (int t = 0; t < 8; t++) {
        int t2 = t + 8;
        uint64_t po = (uint64_t)((t2 >> 2)*1024 + (t2 & 3)*2);
        uint64_t vo = (uint64_t)((t >> 2)*256   + (t & 3)*2);
        mma_f16_ss(dO, pd + po, vd + vo, IDESC_PV, true);
    }
    TCGEN05_COMMIT(mb);
}

__device__ __forceinline__ uint32_t p_off(int r, int c) {
    uint32_t byte = ((uint32_t)(r >> 3) + (uint32_t)(c >> 6)*16u)*1024u
                  + (uint32_t)(r & 7)*128u + (uint32_t)(c & 63)*2u;
    return sw128(byte);
}
__device__ __forceinline__ uint32_t v_off(int n, int c) {
    uint32_t byte = ((uint32_t)(n >> 3) + (uint32_t)(c >> 6)*4u)*1024u
                  + (uint32_t)(n & 7)*128u + (uint32_t)(c & 63)*2u;
    return sw128(byte);
}
__device__ __forceinline__ uint32_t b_off(int n, int c) {
    uint32_t byte = ((uint32_t)(n >> 3) + (uint32_t)(c >> 6)*32u)*1024u
                  + (uint32_t)(n & 7)*128u + (uint32_t)(c & 63)*2u;
    return sw128(byte);
}
__device__ __forceinline__ void split_f8(const float* f, uint4& hi, uint4& lo) {
    uint32_t hh[4], ll[4];
    #pragma unroll
    for (int q = 0; q < 4; q++) {
        float a0 = f[2*q], a1 = f[2*q+1];
        __nv_bfloat162 h2 = __floats2bfloat162_rn(a0, a1);
        float h0 = __low2float(h2), h1 = __high2float(h2);
        __nv_bfloat162 l2 = __floats2bfloat162_rn(a0 - h0, a1 - h1);
        hh[q] = bf2u(h2); ll[q] = bf2u(l2);
    }
    hi = make_uint4(hh[0], hh[1], hh[2], hh[3]);
    lo = make_uint4(ll[0], ll[1], ll[2], ll[3]);
}
__device__ __forceinline__ void split8(const uint32_t* v, uint4& hi, uint4& lo) {
    float f[8];
    #pragma unroll
    for (int j = 0; j < 8; j++) f[j] = __uint_as_float(v[j]);
    split_f8(f, hi, lo);
}
#endif // TC_PATH

// ---------------------------------------------------------------------------
// Baseline fp32 projection (only does work when TC path is unavailable).
// ---------------------------------------------------------------------------
__global__ __launch_bounds__(256) void proj_kernel(
    const float* __restrict__ Xq, const float* __restrict__ Xk, const float* __restrict__ Xv,
    const float* __restrict__ Wq, const float* __restrict__ Wk, const float* __restrict__ Wv)
{
#if TC_PATH
    return;
#else
    __shared__ float As[32][132];
    __shared__ float Bs[32][132];

    const float* X; const float* W;
    if (blockIdx.z == 0)      { X = Xq; W = Wq; }
    else if (blockIdx.z == 1) { X = Xk; W = Wk; }
    else                      { X = Xv; W = Wv; }

    const int tid  = threadIdx.x;
    const int tx   = tid & 15, ty = tid >> 4;
    const int row0 = blockIdx.x * 128;
    const int n0   = blockIdx.y * 128;

    float acc[8][8];
    #pragma unroll
    for (int i = 0; i < 8; i++)
        #pragma unroll
        for (int j = 0; j < 8; j++) acc[i][j] = 0.f;

    for (int k0 = 0; k0 < 256; k0 += 32) {
        #pragma unroll
        for (int t = 0; t < 4; t++) {
            int idx = tid + t*256;
            int r   = idx >> 3;
            int kq  = idx & 7;
            float4 v = *(const float4*)&X[(size_t)(row0 + r)*256 + k0 + kq*4];
            As[kq*4+0][r] = v.x; As[kq*4+1][r] = v.y;
            As[kq*4+2][r] = v.z; As[kq*4+3][r] = v.w;
        }
        #pragma unroll
        for (int t = 0; t < 4; t++) {
            int kd = t*8 + (tid >> 5);
            int ng = tid & 31;
            int n  = n0 + ng*4;
            int h  = n >> 5, kk = n & 31;
            float4 v = *(const float4*)&W[(size_t)h*8192 + (size_t)(k0+kd)*32 + kk];
            *(float4*)&Bs[kd][ng*4] = v;
        }
        __syncthreads();

        #pragma unroll 8
        for (int kk = 0; kk < 32; kk++) {
            float a[8], bv[8];
            *(float4*)&a[0]  = *(float4*)&As[kk][ty*8];
            *(float4*)&a[4]  = *(float4*)&As[kk][ty*8+4];
            *(float4*)&bv[0] = *(float4*)&Bs[kk][tx*8];
            *(float4*)&bv[4] = *(float4*)&Bs[kk][tx*8+4];
            #pragma unroll
            for (int i = 0; i < 8; i++)
                #pragma unroll
                for (int j = 0; j < 8; j++)
                    acc[i][j] += a[i]*bv[j];
        }
        __syncthreads();
    }

    const int n = n0 + tx*8;
    const int h = n >> 5, kk = n & 31;
    float* O;
    if (blockIdx.z == 0)      O = g_q;
    else if (blockIdx.z == 1) O = g_k;
    else                      O = g_v;
    #pragma unroll
    for (int i = 0; i < 8; i++) {
        int m = row0 + ty*8 + i;
        int b = m >> 10, s = m & 1023;
        float* op = &O[(((size_t)(b*HH + h))*SS + s)*DKK + kk];
        *(float4*)op       = make_float4(acc[i][0], acc[i][1], acc[i][2], acc[i][3]);
        *(float4*)(op + 4) = make_float4(acc[i][4], acc[i][5], acc[i][6], acc[i][7]);
    }
#endif
}

// ---------------------------------------------------------------------------
// tcgen05 projection (R12, unchanged): pipelined chunks, register staging.
// ---------------------------------------------------------------------------
#define PJ_A   0
#define PJ_B   32768
#define PJ_MB  98304
#define PJ_TM  98312
#define SMEM_PJ 98336

__global__ __launch_bounds__(512, 1) void proj2_kernel(
    const float* __restrict__ Xq, const float* __restrict__ Xk, const float* __restrict__ Xv,
    const float* __restrict__ Wq, const float* __restrict__ Wk, const float* __restrict__ Wv)
{
#if TC_PATH
    extern __shared__ char smc[];
    const uint32_t smb = smem_u32(smc);
    const int tid = threadIdx.x, wid = tid >> 5, lane = tid & 31;
    const int z = blockIdx.z;

    const float* X; const float* W;
    if (z == 0)      { X = Xq; W = Wq; }
    else if (z == 1) { X = Xk; W = Wk; }
    else             { X = Xv; W = Wv; }

    const int mtile  = blockIdx.y*128 + blockIdx.x;
    const int sblock = blockIdx.x;
    const int half   = blockIdx.y;

    if (wid == 0) TCGEN05_ALLOC(smb + PJ_TM, 256);
    if (tid == 0) MBARRIER_INIT(smb + PJ_MB, 1);
    __syncthreads();
    uint32_t tmem;
    asm volatile("ld.shared.b32 %0, [%1];" : "=r"(tmem) : "r"(smb + PJ_TM));

    const uint64_t adesc = MAKE_DESC(smb + PJ_A);
    const uint64_t bdesc = MAKE_DESC(smb + PJ_B);
    int cnt = 0;

    int aI0[2], aI1[2];
    int bI0[4], bI1[4];
    #pragma unroll
    for (int t = 0; t < 2; t++) {
        int idx = tid + t*512;
        if (z < 2) { aI0[t] = idx >> 3;  aI1[t] = idx & 7; }
        else       { aI0[t] = idx & 127; aI1[t] = idx >> 7; }
    }
    #pragma unroll
    for (int t = 0; t < 4; t++) {
        int idx = tid + t*512;
        if (z < 2) { bI0[t] = idx & 255; bI1[t] = idx >> 8; }
        else       { bI0[t] = idx >> 3;  bI1[t] = idx & 7; }
    }

    float stA[2][8], stB[4][8];

    auto stage = [&](int ch) {
        const int k0 = ch*64;
        if (z < 2) {
            #pragma unroll
            for (int t = 0; t < 2; t++) {
                const float* xp = X + (size_t)(mtile*128 + aI0[t])*256 + k0 + aI1[t]*8;
                *(float4*)&stA[t][0] = *(const float4*)xp;
                *(float4*)&stA[t][4] = *(const float4*)(xp + 4);
            }
            #pragma unroll
            for (int t = 0; t < 4; t++) {
                int n = bI0[t], hh = n >> 5, kk = n & 31;
                const float* wp = W + (size_t)hh*8192 + (size_t)(k0 + bI1[t]*8)*32 + kk;
                #pragma unroll
                for (int j = 0; j < 8; j++) stB[t][j] = wp[j*32];
            }
        } else {
            #pragma unroll
            for (int t = 0; t < 2; t++) {
                int n = half*128 + aI0[t], hh = n >> 5, kk = n & 31;
                const float* wp = W + (size_t)hh*8192 + (size_t)(k0 + aI1[t]*8)*32 + kk;
                #pragma unroll
                for (int j = 0; j < 8; j++) stA[t][j] = wp[j*32];
            }
            #pragma unroll
            for (int t = 0; t < 4; t++) {
                const float* xp = X + (size_t)(sblock*256 + bI0[t])*256 + k0 + bI1[t]*8;
                *(float4*)&stB[t][0] = *(const float4*)xp;
                *(float4*)&stB[t][4] = *(const float4*)(xp + 4);
            }
        }
    };

    stage(0);

    for (int ch = 0; ch < 4; ch++) {
        if (ch) { MBARRIER_WAIT_PARITY(smb + PJ_MB, cnt & 1); cnt++; TCGEN05_FENCE_AFTER(); }

        #pragma unroll
        for (int t = 0; t < 2; t++) {
            uint4 hi, lo; split_f8(stA[t], hi, lo);
            *(uint4*)(smc + PJ_A + p_off(aI0[t], aI1[t]*8))      = hi;
            *(uint4*)(smc + PJ_A + p_off(aI0[t], 64 + aI1[t]*8)) = lo;
        }
        #pragma unroll
        for (int t = 0; t < 4; t++) {
            uint4 hi, lo; split_f8(stB[t], hi, lo);
            *(uint4*)(smc + PJ_B + b_off(bI0[t], bI1[t]*8))      = hi;
            *(uint4*)(smc + PJ_B + b_off(bI0[t], 64 + bI1[t]*8)) = lo;
        }
        FENCE_ASYNC_SHARED();
        __syncthreads();

        if (wid == 0 && elect_one()) {
            #pragma unroll
            for (int ks = 0; ks < 4; ks++)
                mma_f16_ss(tmem, adesc + 2*ks, bdesc + 2*ks, IDESC_PJ, !(ch == 0 && ks == 0));
            #pragma unroll
            for (int ks = 0; ks < 4; ks++)
                mma_f16_ss(tmem, adesc + 2*ks, bdesc + 2048 + 2*ks, IDESC_PJ, true);
            #pragma unroll
            for (int ks = 0; ks < 4; ks++)
                mma_f16_ss(tmem, adesc + 1024 + 2*ks, bdesc + 2*ks, IDESC_PJ, true);
            TCGEN05_COMMIT(smb + PJ_MB);
        }

        if (ch + 1 < 4) stage(ch + 1);
    }
    MBARRIER_WAIT_PARITY(smb + PJ_MB, cnt & 1); cnt++;
    TCGEN05_FENCE_AFTER();

    const int r  = (wid & 3)*32 + lane;
    const int c0 = (wid >> 2)*64;

    #pragma unroll
    for (int hseg = 0; hseg < 2; hseg++) {
        uint32_t d[32];
        TCGEN05_LD_X32(d, tmem + c0 + hseg*32);
        TCGEN05_WAIT_LD();

        if (z < 2) {
            __nv_bfloat16* O = (z == 0) ? g_Qs : g_Ksx;
            int m = mtile*128 + r, b = m >> 10, s = m & 1023;
            #pragma unroll
            for (int g = 0; g < 4; g++) {
                int n = c0 + hseg*32 + g*8;
                int hh = n >> 5, kk = n & 31;
                uint4 hi, lo; split8(d + g*8, hi, lo);
                __nv_bfloat16* op = O + (((size_t)(b*HH + hh))*SS + s)*64 + kk;
                *(uint4*)op        = hi;
                *(uint4*)(op + 32) = lo;
            }
        } else {
            int n = half*128 + r, hh = n >> 5, kk = n & 31;
            int b = sblock >> 2;
            #pragma unroll
            for (int g = 0; g < 4; g++) {
                int c = c0 + hseg*32 + g*8;
                int s_in = (sblock & 3)*256 + c;
                int tile = s_in >> 7, sl = s_in & 127;
                uint4 hi, lo; split8(d + g*8, hi, lo);
                __nv_bfloat16* vp = g_Vt + (((size_t)(b*HH + hh))*8 + tile)*8192
                                  + (size_t)kk*256 + sl;
                *(uint4*)vp         = hi;
                *(uint4*)(vp + 128) = lo;
            }
        }
    }
    __syncthreads();
    if (wid == 0) TCGEN05_DEALLOC(tmem, 256);
#endif
}

// ---------------------------------------------------------------------------
// Attention (R12 base, QK issue moved BEFORE softmax so exp hides QK latency):
// per tile: stage -> MBA wait -> LDTM -> MBB wait -> STS K/V[nbuf] ->
//           fence+sync -> issue QK(kt+1) -> exp/split/P-store -> fence+sync ->
//           issue PV(kt).
// ---------------------------------------------------------------------------
#define SM_Q    0
#define SM_K0   16384
#define SM_K1   32768
#define SM_V0   49152
#define SM_V1   65536
#define SM_P    81920
#define SM_MSK  147456
#define SM_RED  151552
#define SM_LIV  153600
#define SM_MBA  154112
#define SM_MBB  154120
#define SM_TM   154128
#define SMEM_ATTN 154144

__global__ __launch_bounds__(512, 1) void attn_kernel(
    const float* __restrict__ mask, float* __restrict__ out)
{
    extern __shared__ char smc[];
    const int tid  = threadIdx.x;
    const int qb = blockIdx.x, h = blockIdx.y, b = blockIdx.z;

#if TC_PATH
    const uint32_t smb = smem_u32(smc);
    const int wid  = tid >> 5;
    const int lane = tid & 31;
    const int r  = (wid & 3)*32 + lane;
    const int c0 = (wid >> 2)*32;

    if (wid == 0) TCGEN05_ALLOC(smb + SM_TM, 512);
    if (tid == 0) { MBARRIER_INIT(smb + SM_MBA, 1); MBARRIER_INIT(smb + SM_MBB, 1); }

    const size_t bh = (size_t)(b*HH + h);
    const uint4* qg = (const uint4*)(g_Qs + bh*(SS*64) + (size_t)qb*128*64);
    const __nv_bfloat16* kgb = g_Ksx + bh*(SS*64);
    const __nv_bfloat16* vgb = g_Vt  + bh*(8*32*256);

    const int it0 = tid, it1 = tid + 512;
    const int k_rr0 = it0 >> 3, k_ch0 = it0 & 7;
    const int k_rr1 = it1 >> 3, k_ch1 = it1 & 7;
    const int v_n0 = it0 >> 5, v_c0 = (it0 & 31)*8;
    const int v_n1 = it1 >> 5, v_c1 = (it1 & 31)*8;

    for (int it = tid; it < 1024; it += 512) {
        int rr = it >> 3, ch = it & 7;
        *(uint4*)(smc + SM_Q + sw128(rr*128 + ch*16)) = qg[it];
    }
    if (tid < 256) ((uint4*)(smc + SM_MSK))[tid] = ((const uint4*)(mask + (size_t)b*SS))[tid];
    {
        const uint4* kg = (const uint4*)(kgb);
        const uint4* vg = (const uint4*)(vgb);
        *(uint4*)(smc + SM_K0 + sw128(k_rr0*128 + k_ch0*16)) = kg[it0];
        *(uint4*)(smc + SM_K0 + sw128(k_rr1*128 + k_ch1*16)) = kg[it1];
        *(uint4*)(smc + SM_V0 + v_off(v_n0, v_c0)) = vg[it0];
        *(uint4*)(smc + SM_V0 + v_off(v_n1, v_c1)) = vg[it1];
    }
    FENCE_ASYNC_SHARED();
    __syncthreads();

    uint32_t tmem;
    asm volatile("ld.shared.b32 %0, [%1];" : "=r"(tmem) : "r"(smb + SM_TM));
    const uint32_t dS[2] = { tmem, tmem + 128 };
    const uint32_t dO = tmem + 256;

    const float* Msk = (const float*)(smc + SM_MSK);
    const uint64_t qdesc = MAKE_DESC(smb + SM_Q);
    const uint64_t pdesc = MAKE_DESC(smb + SM_P);
    const uint64_t kdesc[2] = { MAKE_DESC(smb + SM_K0), MAKE_DESC(smb + SM_K1) };
    const uint64_t vdesc[2] = { MAKE_DESC(smb + SM_V0), MAKE_DESC(smb + SM_V1) };
    const uint32_t smKoff[2] = { SM_K0, SM_K1 };
    const uint32_t smVoff[2] = { SM_V0, SM_V1 };

    if (wid == 0 && elect_one()) {
        issue_qk(dS[0], qdesc, kdesc[0], smb + SM_MBA);
    }

    int cntA = 0, cntB = 0;
    float lacc = 0.0f;

    for (int kt = 0; kt < 8; kt++) {
        const int buf = kt & 1, nbuf = buf ^ 1;

        // 1. stage K/V(kt+1)
        uint4 kreg0, kreg1, vreg0, vreg1;
        if (kt + 1 < 8) {
            const uint4* kg = (const uint4*)(kgb + (size_t)(kt + 1)*128*64);
            const uint4* vg = (const uint4*)(vgb + (size_t)(kt + 1)*32*256);
            kreg0 = kg[it0]; kreg1 = kg[it1];
            vreg0 = vg[it0]; vreg1 = vg[it1];
        }

        // 2. QK(kt) done -> S[buf] valid
        MBARRIER_WAIT_PARITY(smb + SM_MBA, cntA & 1); cntA++;
        TCGEN05_FENCE_AFTER();

        // 3. read scores (keep in regs)
        uint32_t sregs[32];
        TCGEN05_LD_X32(sregs, dS[buf] + c0);
        TCGEN05_WAIT_LD();

        // 4. PV(kt-1) done -> P smem and K/V[nbuf] reusable
        if (kt) { MBARRIER_WAIT_PARITY(smb + SM_MBB, cntB & 1); cntB++; }

        // 5. store staged K/V tile kt+1 into buffers [nbuf]
        if (kt + 1 < 8) {
            *(uint4*)(smc + smKoff[nbuf] + sw128(k_rr0*128 + k_ch0*16)) = kreg0;
            *(uint4*)(smc + smKoff[nbuf] + sw128(k_rr1*128 + k_ch1*16)) = kreg1;
            *(uint4*)(smc + smVoff[nbuf] + v_off(v_n0, v_c0)) = vreg0;
            *(uint4*)(smc + smVoff[nbuf] + v_off(v_n1, v_c1)) = vreg1;
        }

        // 6. fence+sync: K[nbuf] visible; all warps past both waits & LDTM
        FENCE_ASYNC_SHARED();
        __syncthreads();

        // 7. issue QK(kt+1) NOW -- the softmax below hides its latency
        if (kt + 1 < 8 && wid == 0 && elect_one())
            issue_qk(dS[nbuf], qdesc, kdesc[nbuf], smb + SM_MBA);

        // 8. exp + split-bf16 P store (overlaps QK(kt+1))
        float p[32];
        #pragma unroll
        for (int j = 0; j < 32; j++) {
            float m  = Msk[kt*128 + c0 + j];
            float sv = fmaf(m, __uint_as_float(sregs[j]), (m - 1.0f)*1e-30f);
            p[j] = __expf(sv - 40.0f);
            lacc += p[j];
        }
        #pragma unroll
        for (int g = 0; g < 4; g++) {
            uint32_t hp[4], lp[4];
            #pragma unroll
            for (int q = 0; q < 4; q++) {
                float a0 = p[g*8 + 2*q], a1 = p[g*8 + 2*q + 1];
                __nv_bfloat162 hh = __floats2bfloat162_rn(a0, a1);
                float h0 = __low2float(hh), h1 = __high2float(hh);
                __nv_bfloat162 ll = __floats2bfloat162_rn(a0 - h0, a1 - h1);
                hp[q] = bf2u(hh); lp[q] = bf2u(ll);
            }
            *(uint4*)(smc + SM_P + p_off(r, c0 + g*8))       = make_uint4(hp[0], hp[1], hp[2], hp[3]);
            *(uint4*)(smc + SM_P + p_off(r, 128 + c0 + g*8)) = make_uint4(lp[0], lp[1], lp[2], lp[3]);
        }

        // 9. fence+sync: P visible; all warps past MBB wait (step 4)
        FENCE_ASYNC_SHARED();
        __syncthreads();

        // 10. issue PV(kt); waited next iteration (step 4)
        if (wid == 0 && elect_one())
            issue_pv(dO, pdesc, vdesc[buf], kt == 0, smb + SM_MBB);
    }
    MBARRIER_WAIT_PARITY(smb + SM_MBB, cntB & 1); cntB++;
    TCGEN05_FENCE_AFTER();

    ((float*)(smc + SM_RED))[(wid >> 2)*128 + r] = lacc;
    __syncthreads();
    if (tid < 128) {
        const float* rd = (const float*)(smc + SM_RED);
        ((float*)(smc + SM_LIV))[tid] =
            1.0f / (rd[tid] + rd[128 + tid] + rd[256 + tid] + rd[384 + tid]);
    }
    __syncthreads();

    if (wid < 4) {
        uint32_t oregs[32];
        TCGEN05_LD_X32(oregs, dO);
        TCGEN05_WAIT_LD();
        float inv = ((float*)(smc + SM_LIV))[r];
        float* op = out + (((size_t)b*SS) + qb*128 + r)*256 + h*32;
        #pragma unroll
        for (int g = 0; g < 8; g++) {
            float4 v;
            v.x = __uint_as_float(oregs[g*4+0])*inv;
            v.y = __uint_as_float(oregs[g*4+1])*inv;
            v.z = __uint_as_float(oregs[g*4+2])*inv;
            v.w = __uint_as_float(oregs[g*4+3])*inv;
            *(float4*)(op + g*4) = v;
        }
    }
    __syncthreads();
    if (wid == 0) TCGEN05_DEALLOC(tmem, 512);

#else  // ===================== baseline FFMA flash (512 threads) =====================
    float* sm = (float*)smc;
    float* Qt = sm;
    float* Kt = Qt + 32*132;
    float* Vs = Kt + 32*68;
    float* Ps = Vs + 64*32;
    float* Ms = Ps + 128*68;

    const int tx = tid & 15, ty = tid >> 4;

    const float* qptr = g_q + (((size_t)(b*HH + h))*SS + qb*128)*DKK;
    for (int idx = tid; idx < 128*32; idx += 512) {
        int d = idx & 31, rr = idx >> 5;
        Qt[d*132 + rr] = qptr[idx];
    }

    float m_i[4], l_i[4], o0[4], o1[4];
    #pragma unroll
    for (int i = 0; i < 4; i++) { m_i[i] = -1e38f; l_i[i] = 0.f; o0[i] = 0.f; o1[i] = 0.f; }

    const float* kbase = g_k + ((size_t)(b*HH + h))*SS*DKK;
    const float* vbase = g_v + ((size_t)(b*HH + h))*SS*DKK;
    const float* mbase = mask + (size_t)b*SS;

    for (int kt = 0; kt < 16; kt++) {
        __syncthreads();
        const float* kp = kbase + (size_t)kt*64*32;
        for (int idx = tid; idx < 64*32; idx += 512) {
            int d = idx & 31, rr = idx >> 5;
            Kt[d*68 + rr] = kp[idx];
        }
        const float4* vp = (const float4*)(vbase + (size_t)kt*64*32);
        for (int idx = tid; idx < 64*32/4; idx += 512)
            ((float4*)Vs)[idx] = vp[idx];
        if (tid < 64) Ms[tid] = mbase[kt*64 + tid];
        __syncthreads();

        float sc[4][4];
        #pragma unroll
        for (int i = 0; i < 4; i++)
            #pragma unroll
            for (int j = 0; j < 4; j++) sc[i][j] = 0.f;

        #pragma unroll 8
        for (int d = 0; d < 32; d++) {
            float a[4], kv[4];
            *(float4*)&a[0]  = *(float4*)&Qt[d*132 + ty*4];
            *(float4*)&kv[0] = *(float4*)&Kt[d*68 + tx*4];
            #pragma unroll
            for (int i = 0; i < 4; i++)
                #pragma unroll
                for (int j = 0; j < 4; j++)
                    sc[i][j] += a[i]*kv[j];
        }

        float mv[4];
        #pragma unroll
        for (int j = 0; j < 4; j++) mv[j] = Ms[tx*4 + j];

        #pragma unroll
        for (int i = 0; i < 4; i++) {
            #pragma unroll
            for (int j = 0; j < 4; j++)
                sc[i][j] = mv[j]*sc[i][j] + (1.f - mv[j])*(-1e-30f);

            float tm = fmaxf(fmaxf(sc[i][0], sc[i][1]), fmaxf(sc[i][2], sc[i][3]));
            #pragma unroll
            for (int off = 8; off > 0; off >>= 1)
                tm = fmaxf(tm, __shfl_xor_sync(0xffffffffu, tm, off));

            float mnew = fmaxf(m_i[i], tm);
            float rs = 0.f;
            #pragma unroll
            for (int j = 0; j < 4; j++) {
                float pp = __expf(sc[i][j] - mnew);
                sc[i][j] = pp;
                rs += pp;
            }
            #pragma unroll
            for (int off = 8; off > 0; off >>= 1)
                rs += __shfl_xor_sync(0xffffffffu, rs, off);

            float alpha = __expf(m_i[i] - mnew);
            l_i[i] = l_i[i]*alpha + rs;
            m_i[i] = mnew;
            o0[i] *= alpha;
            o1[i] *= alpha;

            *(float4*)&Ps[(ty*4+i)*68 + tx*4] =
                make_float4(sc[i][0], sc[i][1], sc[i][2], sc[i][3]);
        }
        __syncthreads();

        #pragma unroll 4
        for (int s0 = 0; s0 < 64; s0 += 4) {
            float2 v0 = *(float2*)&Vs[(s0+0)*32 + tx*2];
            float2 v1 = *(float2*)&Vs[(s0+1)*32 + tx*2];
            float2 v2 = *(float2*)&Vs[(s0+2)*32 + tx*2];
            float2 v3 = *(float2*)&Vs[(s0+3)*32 + tx*2];
            #pragma unroll
            for (int i = 0; i < 4; i++) {
                float4 pp = *(float4*)&Ps[(ty*4+i)*68 + s0];
                o0[i] += pp.x*v0.x + pp.y*v1.x + pp.z*v2.x + pp.w*v3.x;
                o1[i] += pp.x*v0.y + pp.y*v1.y + pp.z*v2.y + pp.w*v3.y;
            }
        }
    }

    #pragma unroll
    for (int i = 0; i < 4; i++) {
        float inv = 1.f / l_i[i];
        int row = qb*128 + ty*4 + i;
        float2 res = make_float2(o0[i]*inv, o1[i]*inv);
        *(float2*)&out[((size_t)b*SS + row)*256 + h*32 + tx*2] = res;
    }
#endif
}

// ---------------------------------------------------------------------------
extern "C" void kernel_launch(void* const* d_in, const int* in_sizes, int n_in,
                              void* d_out, int out_size)
{
    (void)in_sizes; (void)n_in; (void)out_size;
    const float* query = (const float*)d_in[0];
    const float* key   = (const float*)d_in[1];
    const float* value = (const float*)d_in[2];
    const float* mask  = (const float*)d_in[3];
    const float* Wq    = (const float*)d_in[4];
    const float* Wk    = (const float*)d_in[5];
    const float* Wv    = (const float*)d_in[6];
    float* out = (float*)d_out;

    cudaFuncSetAttribute(attn_kernel,
                         cudaFuncAttributeMaxDynamicSharedMemorySize, SMEM_ATTN);
    cudaFuncSetAttribute(proj2_kernel,
                         cudaFuncAttributeMaxDynamicSharedMemorySize, SMEM_PJ);

    proj_kernel<<<dim3(256, 2, 3), 256>>>(query, key, value, Wq, Wk, Wv);
    proj2_kernel<<<dim3(128, 2, 3), 512, SMEM_PJ>>>(query, key, value, Wq, Wk, Wv);
    attn_kernel<<<dim3(8, 8, 32), 512, SMEM_ATTN>>>(mask, out);
}

// round 17
// speedup vs baseline: 1.0890x; 1.0492x over previous
#include <cuda_runtime.h>
#include <cuda_bf16.h>
#include <cstdint>
#include <math.h>

#if defined(__CUDA_ARCH_FEAT_SM103_ALL) || defined(__CUDA_ARCH_FEAT_SM100_ALL)
#define TC_PATH 1
#else
#define TC_PATH 0
#endif

#define BB  32
#define SS  1024
#define DD  256
#define HH  8
#define DKK 32

// ---------------- fp32 scratch (baseline fallback path) ----------------
__device__ float g_q[BB*HH*SS*DKK];
__device__ float g_k[BB*HH*SS*DKK];
__device__ float g_v[BB*HH*SS*DKK];

// ---------------- split-bf16 scratch (tcgen05 path) ----------------
__device__ __nv_bfloat16 g_Qs[BB*HH*SS*64];
__device__ __nv_bfloat16 g_Ksx[BB*HH*SS*64];
__device__ __nv_bfloat16 g_Vt[BB*HH*8*32*256];

// ======================= common helpers =======================
__device__ __forceinline__ uint32_t smem_u32(const void* p) {
    uint32_t a;
    asm("{ .reg .u64 t; cvta.to.shared.u64 t, %1; cvt.u32.u64 %0, t; }" : "=r"(a) : "l"(p));
    return a;
}
__device__ __forceinline__ uint32_t sw128(uint32_t b) { return b ^ ((b >> 3) & 0x70); }
__device__ __forceinline__ uint32_t bf2u(__nv_bfloat162 v) {
    union { __nv_bfloat162 b; uint32_t u; } cv; cv.b = v; return cv.u;
}

#if TC_PATH
// ======================= tcgen05 helpers (sm_103a only) =======================
__device__ __forceinline__ uint32_t elect_one() {
    uint32_t pred;
    asm volatile("{\n\t.reg .pred p;\n\telect.sync _|p, 0xFFFFFFFF;\n\tselp.b32 %0, 1, 0, p;\n\t}" : "=r"(pred));
    return pred;
}
#define TCGEN05_ALLOC(sa, n) \
    asm volatile("tcgen05.alloc.cta_group::1.sync.aligned.shared::cta.b32 [%0], %1;" \
        :: "r"((uint32_t)(sa)), "r"((uint32_t)(n)) : "memory")
#define TCGEN05_DEALLOC(t, n) \
    asm volatile("tcgen05.dealloc.cta_group::1.sync.aligned.b32 %0, %1;" :: "r"(t), "r"((uint32_t)(n)))
#define TCGEN05_COMMIT(mb) \
    asm volatile("tcgen05.commit.cta_group::1.mbarrier::arrive::one.shared::cluster.b64 [%0];" \
        :: "r"((uint32_t)(mb)) : "memory")
#define TCGEN05_WAIT_LD()  asm volatile("tcgen05.wait::ld.sync.aligned;" ::: "memory")
#define TCGEN05_FENCE_AFTER()  asm volatile("tcgen05.fence::after_thread_sync;" ::: "memory")
#define FENCE_ASYNC_SHARED() asm volatile("fence.proxy.async.shared::cta;" ::: "memory")
#define MBARRIER_INIT(mb, c) \
    asm volatile("mbarrier.init.shared.b64 [%0], %1;" :: "r"((uint32_t)(mb)), "r"((uint32_t)(c)) : "memory")
#define MBARRIER_WAIT_PARITY(mb, ph) do { \
    uint32_t _m = (uint32_t)(mb), _p = (uint32_t)(ph), _d; \
    asm volatile("{\n\t.reg .pred p;\n\t" \
        "mbarrier.try_wait.parity.acquire.cta.shared::cta.b64 p, [%1], %2;\n\t" \
        "selp.b32 %0, 1, 0, p;\n\t}" : "=r"(_d) : "r"(_m), "r"(_p) : "memory"); \
    if (!_d) { \
        asm volatile("{\n\t.reg .pred P1;\n\t" \
            "WL_%=:\n\t" \
            "mbarrier.try_wait.parity.acquire.cta.shared::cta.b64 P1, [%0], %1, 0x989680;\n\t" \
            "@P1 bra.uni WD_%=;\n\tbra.uni WL_%=;\n\tWD_%=:\n\t}" \
            :: "r"(_m), "r"(_p) : "memory"); \
    } } while (0)
#define TCGEN05_LD_X32(r, ta) \
    asm volatile("tcgen05.ld.sync.aligned.32x32b.x32.b32 " \
        "{%0, %1, %2, %3, %4, %5, %6, %7, %8, %9, %10, %11, %12, %13, %14, %15, " \
        " %16, %17, %18, %19, %20, %21, %22, %23, %24, %25, %26, %27, %28, %29, %30, %31}, [%32];" \
        : "=r"((r)[0]),  "=r"((r)[1]),  "=r"((r)[2]),  "=r"((r)[3]), \
          "=r"((r)[4]),  "=r"((r)[5]),  "=r"((r)[6]),  "=r"((r)[7]), \
          "=r"((r)[8]),  "=r"((r)[9]),  "=r"((r)[10]), "=r"((r)[11]), \
          "=r"((r)[12]), "=r"((r)[13]), "=r"((r)[14]), "=r"((r)[15]), \
          "=r"((r)[16]), "=r"((r)[17]), "=r"((r)[18]), "=r"((r)[19]), \
          "=r"((r)[20]), "=r"((r)[21]), "=r"((r)[22]), "=r"((r)[23]), \
          "=r"((r)[24]), "=r"((r)[25]), "=r"((r)[26]), "=r"((r)[27]), \
          "=r"((r)[28]), "=r"((r)[29]), "=r"((r)[30]), "=r"((r)[31]) \
        : "r"(ta))

static constexpr uint64_t DESC_BASE_SW128 =
    (uint64_t(2) << 61) | (uint64_t(1) << 46) | (uint64_t(64) << 32) | (uint64_t(1) << 16);
#define MAKE_DESC(a) (DESC_BASE_SW128 | ((uint64_t)((a) >> 4) & 0x3FFF))

__device__ __forceinline__ void mma_f16_ss(uint32_t d, uint64_t ad, uint64_t bd,
                                           uint32_t idesc, bool acc) {
    uint32_t en = acc ? 1u : 0u, z = 0u;
    asm volatile(
        "{\n\t.reg .pred p;\n\tsetp.ne.u32 p, %4, 0;\n\t"
        "tcgen05.mma.cta_group::1.kind::f16 [%0], %1, %2, %3, {%5, %5, %5, %5}, p;\n\t}"
        :: "r"(d), "l"(ad), "l"(bd), "r"(idesc), "r"(en), "r"(z) : "memory");
}

// idesc: F32 acc | bf16 A | bf16 B | N | M=128
#define IDESC_QK (0x10u | 0x80u | 0x400u | (16u << 17) | (8u << 24))   /* N=128 */
#define IDESC_PV (0x10u | 0x80u | 0x400u | (4u  << 17) | (8u << 24))   /* N=32  */
#define IDESC_PJ (0x10u | 0x80u | 0x400u | (32u << 17) | (8u << 24))   /* N=256 */

// 6-term split-bf16 QK (hi.hi + hi.lo + lo.hi), then commit
__device__ __forceinline__ void issue_qk(uint32_t dS, uint64_t qd, uint64_t kd, uint32_t mb) {
    mma_f16_ss(dS, qd + 0, kd + 0, IDESC_QK, false);
    mma_f16_ss(dS, qd + 2, kd + 2, IDESC_QK, true);
    mma_f16_ss(dS, qd + 0, kd + 4, IDESC_QK, true);
    mma_f16_ss(dS, qd + 2, kd + 6, IDESC_QK, true);
    mma_f16_ss(dS, qd + 4, kd + 0, IDESC_QK, true);
    mma_f16_ss(dS, qd + 6, kd + 2, IDESC_QK, true);
    TCGEN05_COMMIT(mb);
}
// 24-term split-bf16 PV, then commit
__device__ __forceinline__ void issue_pv(uint32_t dO, uint64_t pd, uint64_t vd,
                                         bool first, uint32_t mb) {
    #pragma unroll
    for (int t = 0; t < 8; t++) {
        uint64_t po = (uint64_t)((t >> 2)*1024 + (t & 3)*2);
        uint64_t vo = (uint64_t)((t >> 2)*256  + (t & 3)*2);
        mma_f16_ss(dO, pd + po, vd + vo, IDESC_PV, !(first && t == 0));
    }
    #pragma unroll
    for (int t = 0; t < 8; t++) {
        uint64_t po = (uint64_t)((t >> 2)*1024 + (t & 3)*2);
        int t2 = t + 8;
        uint64_t vo = (uint64_t)((t2 >> 2)*256 + (t2 & 3)*2);
        mma_f16_ss(dO, pd + po, vd + vo, IDESC_PV, true);
    }
    #pragma unroll
    for (int t = 0; t < 8; t++) {
        int t2 = t + 8;
        uint64_t po = (uint64_t)((t2 >> 2)*1024 + (t2 & 3)*2);
        uint64_t vo = (uint64_t)((t >> 2)*256   + (t & 3)*2);
        mma_f16_ss(dO, pd + po, vd + vo, IDESC_PV, true);
    }
    TCGEN05_COMMIT(mb);
}

__device__ __forceinline__ uint32_t p_off(int r, int c) {
    uint32_t byte = ((uint32_t)(r >> 3) + (uint32_t)(c >> 6)*16u)*1024u
                  + (uint32_t)(r & 7)*128u + (uint32_t)(c & 63)*2u;
    return sw128(byte);
}
__device__ __forceinline__ uint32_t v_off(int n, int c) {
    uint32_t byte = ((uint32_t)(n >> 3) + (uint32_t)(c >> 6)*4u)*1024u
                  + (uint32_t)(n & 7)*128u + (uint32_t)(c & 63)*2u;
    return sw128(byte);
}
__device__ __forceinline__ uint32_t b_off(int n, int c) {
    uint32_t byte = ((uint32_t)(n >> 3) + (uint32_t)(c >> 6)*32u)*1024u
                  + (uint32_t)(n & 7)*128u + (uint32_t)(c & 63)*2u;
    return sw128(byte);
}
__device__ __forceinline__ void split_f8(const float* f, uint4& hi, uint4& lo) {
    uint32_t hh[4], ll[4];
    #pragma unroll
    for (int q = 0; q < 4; q++) {
        float a0 = f[2*q], a1 = f[2*q+1];
        __nv_bfloat162 h2 = __floats2bfloat162_rn(a0, a1);
        float h0 = __low2float(h2), h1 = __high2float(h2);
        __nv_bfloat162 l2 = __floats2bfloat162_rn(a0 - h0, a1 - h1);
        hh[q] = bf2u(h2); ll[q] = bf2u(l2);
    }
    hi = make_uint4(hh[0], hh[1], hh[2], hh[3]);
    lo = make_uint4(ll[0], ll[1], ll[2], ll[3]);
}
__device__ __forceinline__ void split8(const uint32_t* v, uint4& hi, uint4& lo) {
    float f[8];
    #pragma unroll
    for (int j = 0; j < 8; j++) f[j] = __uint_as_float(v[j]);
    split_f8(f, hi, lo);
}
#endif // TC_PATH

// ---------------------------------------------------------------------------
// Baseline fp32 projection (only does work when TC path is unavailable).
// ---------------------------------------------------------------------------
__global__ __launch_bounds__(256) void proj_kernel(
    const float* __restrict__ Xq, const float* __restrict__ Xk, const float* __restrict__ Xv,
    const float* __restrict__ Wq, const float* __restrict__ Wk, const float* __restrict__ Wv)
{
#if TC_PATH
    return;
#else
    __shared__ float As[32][132];
    __shared__ float Bs[32][132];

    const float* X; const float* W;
    if (blockIdx.z == 0)      { X = Xq; W = Wq; }
    else if (blockIdx.z == 1) { X = Xk; W = Wk; }
    else                      { X = Xv; W = Wv; }

    const int tid  = threadIdx.x;
    const int tx   = tid & 15, ty = tid >> 4;
    const int row0 = blockIdx.x * 128;
    const int n0   = blockIdx.y * 128;

    float acc[8][8];
    #pragma unroll
    for (int i = 0; i < 8; i++)
        #pragma unroll
        for (int j = 0; j < 8; j++) acc[i][j] = 0.f;

    for (int k0 = 0; k0 < 256; k0 += 32) {
        #pragma unroll
        for (int t = 0; t < 4; t++) {
            int idx = tid + t*256;
            int r   = idx >> 3;
            int kq  = idx & 7;
            float4 v = *(const float4*)&X[(size_t)(row0 + r)*256 + k0 + kq*4];
            As[kq*4+0][r] = v.x; As[kq*4+1][r] = v.y;
            As[kq*4+2][r] = v.z; As[kq*4+3][r] = v.w;
        }
        #pragma unroll
        for (int t = 0; t < 4; t++) {
            int kd = t*8 + (tid >> 5);
            int ng = tid & 31;
            int n  = n0 + ng*4;
            int h  = n >> 5, kk = n & 31;
            float4 v = *(const float4*)&W[(size_t)h*8192 + (size_t)(k0+kd)*32 + kk];
            *(float4*)&Bs[kd][ng*4] = v;
        }
        __syncthreads();

        #pragma unroll 8
        for (int kk = 0; kk < 32; kk++) {
            float a[8], bv[8];
            *(float4*)&a[0]  = *(float4*)&As[kk][ty*8];
            *(float4*)&a[4]  = *(float4*)&As[kk][ty*8+4];
            *(float4*)&bv[0] = *(float4*)&Bs[kk][tx*8];
            *(float4*)&bv[4] = *(float4*)&Bs[kk][tx*8+4];
            #pragma unroll
            for (int i = 0; i < 8; i++)
                #pragma unroll
                for (int j = 0; j < 8; j++)
                    acc[i][j] += a[i]*bv[j];
        }
        __syncthreads();
    }

    const int n = n0 + tx*8;
    const int h = n >> 5, kk = n & 31;
    float* O;
    if (blockIdx.z == 0)      O = g_q;
    else if (blockIdx.z == 1) O = g_k;
    else                      O = g_v;
    #pragma unroll
    for (int i = 0; i < 8; i++) {
        int m = row0 + ty*8 + i;
        int b = m >> 10, s = m & 1023;
        float* op = &O[(((size_t)(b*HH + h))*SS + s)*DKK + kk];
        *(float4*)op       = make_float4(acc[i][0], acc[i][1], acc[i][2], acc[i][3]);
        *(float4*)(op + 4) = make_float4(acc[i][4], acc[i][5], acc[i][6], acc[i][7]);
    }
#endif
}

// ---------------------------------------------------------------------------
// tcgen05 projection: R12's exact single-buffer/single-mbarrier structure,
// but the split-bf16 CONVERSION is done into registers BEFORE the MMA wait
// (while MMA(ch-1) runs); only the cheap STS remains after the wait.
// Per chunk: [wait residue~0] STS -> fence+sync -> issue MMA(ch) ->
//            stage LDG(ch+1) + convert-to-regs (overlaps MMA(ch)).
// ---------------------------------------------------------------------------
#define PJ_A   0
#define PJ_B   32768
#define PJ_MB  98304
#define PJ_TM  98312
#define SMEM_PJ 98336

__global__ __launch_bounds__(512, 1) void proj2_kernel(
    const float* __restrict__ Xq, const float* __restrict__ Xk, const float* __restrict__ Xv,
    const float* __restrict__ Wq, const float* __restrict__ Wk, const float* __restrict__ Wv)
{
#if TC_PATH
    extern __shared__ char smc[];
    const uint32_t smb = smem_u32(smc);
    const int tid = threadIdx.x, wid = tid >> 5, lane = tid & 31;
    const int z = blockIdx.z;

    const float* X; const float* W;
    if (z == 0)      { X = Xq; W = Wq; }
    else if (z == 1) { X = Xk; W = Wk; }
    else             { X = Xv; W = Wv; }

    const int mtile  = blockIdx.y*128 + blockIdx.x;
    const int sblock = blockIdx.x;
    const int half   = blockIdx.y;

    if (wid == 0) TCGEN05_ALLOC(smb + PJ_TM, 256);
    if (tid == 0) MBARRIER_INIT(smb + PJ_MB, 1);
    __syncthreads();
    uint32_t tmem;
    asm volatile("ld.shared.b32 %0, [%1];" : "=r"(tmem) : "r"(smb + PJ_TM));

    const uint64_t adesc = MAKE_DESC(smb + PJ_A);
    const uint64_t bdesc = MAKE_DESC(smb + PJ_B);
    int cnt = 0;

    int aI0[2], aI1[2];
    int bI0[4], bI1[4];
    #pragma unroll
    for (int t = 0; t < 2; t++) {
        int idx = tid + t*512;
        if (z < 2) { aI0[t] = idx >> 3;  aI1[t] = idx & 7; }
        else       { aI0[t] = idx & 127; aI1[t] = idx >> 7; }
    }
    #pragma unroll
    for (int t = 0; t < 4; t++) {
        int idx = tid + t*512;
        if (z < 2) { bI0[t] = idx & 255; bI1[t] = idx >> 8; }
        else       { bI0[t] = idx >> 3;  bI1[t] = idx & 7; }
    }

    // converted-register staging for the CURRENT chunk (ready to STS)
    uint4 cvA[2][2];   // [slot][hi/lo]
    uint4 cvB[4][2];

    // LDG + split-convert chunk ch into cvA/cvB (no smem touched)
    auto stage_convert = [&](int ch) {
        const int k0 = ch*64;
        if (z < 2) {
            #pragma unroll
            for (int t = 0; t < 2; t++) {
                float f[8];
                const float* xp = X + (size_t)(mtile*128 + aI0[t])*256 + k0 + aI1[t]*8;
                *(float4*)&f[0] = *(const float4*)xp;
                *(float4*)&f[4] = *(const float4*)(xp + 4);
                split_f8(f, cvA[t][0], cvA[t][1]);
            }
            #pragma unroll
            for (int t = 0; t < 4; t++) {
                float f[8];
                int n = bI0[t], hh = n >> 5, kk = n & 31;
                const float* wp = W + (size_t)hh*8192 + (size_t)(k0 + bI1[t]*8)*32 + kk;
                #pragma unroll
                for (int j = 0; j < 8; j++) f[j] = wp[j*32];
                split_f8(f, cvB[t][0], cvB[t][1]);
            }
        } else {
            #pragma unroll
            for (int t = 0; t < 2; t++) {
                float f[8];
                int n = half*128 + aI0[t], hh = n >> 5, kk = n & 31;
                const float* wp = W + (size_t)hh*8192 + (size_t)(k0 + aI1[t]*8)*32 + kk;
                #pragma unroll
                for (int j = 0; j < 8; j++) f[j] = wp[j*32];
                split_f8(f, cvA[t][0], cvA[t][1]);
            }
            #pragma unroll
            for (int t = 0; t < 4; t++) {
                float f[8];
                const float* xp = X + (size_t)(sblock*256 + bI0[t])*256 + k0 + bI1[t]*8;
                *(float4*)&f[0] = *(const float4*)xp;
                *(float4*)&f[4] = *(const float4*)(xp + 4);
                split_f8(f, cvB[t][0], cvB[t][1]);
            }
        }
    };
    // STS the converted chunk from registers into the (free) smem buffers
    auto sts_chunk = [&]() {
        #pragma unroll
        for (int t = 0; t < 2; t++) {
            *(uint4*)(smc + PJ_A + p_off(aI0[t], aI1[t]*8))      = cvA[t][0];
            *(uint4*)(smc + PJ_A + p_off(aI0[t], 64 + aI1[t]*8)) = cvA[t][1];
        }
        #pragma unroll
        for (int t = 0; t < 4; t++) {
            *(uint4*)(smc + PJ_B + b_off(bI0[t], bI1[t]*8))      = cvB[t][0];
            *(uint4*)(smc + PJ_B + b_off(bI0[t], 64 + bI1[t]*8)) = cvB[t][1];
        }
    };

    stage_convert(0);

    for (int ch = 0; ch < 4; ch++) {
        // MMA(ch-1) must finish before overwriting smem A/B (residue ~0:
        // the convert for this chunk already ran while that MMA executed)
        if (ch) { MBARRIER_WAIT_PARITY(smb + PJ_MB, cnt & 1); cnt++; TCGEN05_FENCE_AFTER(); }

        sts_chunk();
        FENCE_ASYNC_SHARED();
        __syncthreads();

        if (wid == 0 && elect_one()) {
            #pragma unroll
            for (int ks = 0; ks < 4; ks++)
                mma_f16_ss(tmem, adesc + 2*ks, bdesc + 2*ks, IDESC_PJ, !(ch == 0 && ks == 0));
            #pragma unroll
            for (int ks = 0; ks < 4; ks++)
                mma_f16_ss(tmem, adesc + 2*ks, bdesc + 2048 + 2*ks, IDESC_PJ, true);
            #pragma unroll
            for (int ks = 0; ks < 4; ks++)
                mma_f16_ss(tmem, adesc + 1024 + 2*ks, bdesc + 2*ks, IDESC_PJ, true);
            TCGEN05_COMMIT(smb + PJ_MB);
        }

        // stage + convert chunk ch+1 while MMA(ch) runs
        if (ch + 1 < 4) stage_convert(ch + 1);
    }
    MBARRIER_WAIT_PARITY(smb + PJ_MB, cnt & 1); cnt++;
    TCGEN05_FENCE_AFTER();

    const int r  = (wid & 3)*32 + lane;
    const int c0 = (wid >> 2)*64;

    #pragma unroll
    for (int hseg = 0; hseg < 2; hseg++) {
        uint32_t d[32];
        TCGEN05_LD_X32(d, tmem + c0 + hseg*32);
        TCGEN05_WAIT_LD();

        if (z < 2) {
            __nv_bfloat16* O = (z == 0) ? g_Qs : g_Ksx;
            int m = mtile*128 + r, b = m >> 10, s = m & 1023;
            #pragma unroll
            for (int g = 0; g < 4; g++) {
                int n = c0 + hseg*32 + g*8;
                int hh = n >> 5, kk = n & 31;
                uint4 hi, lo; split8(d + g*8, hi, lo);
                __nv_bfloat16* op = O + (((size_t)(b*HH + hh))*SS + s)*64 + kk;
                *(uint4*)op        = hi;
                *(uint4*)(op + 32) = lo;
            }
        } else {
            int n = half*128 + r, hh = n >> 5, kk = n & 31;
            int b = sblock >> 2;
            #pragma unroll
            for (int g = 0; g < 4; g++) {
                int c = c0 + hseg*32 + g*8;
                int s_in = (sblock & 3)*256 + c;
                int tile = s_in >> 7, sl = s_in & 127;
                uint4 hi, lo; split8(d + g*8, hi, lo);
                __nv_bfloat16* vp = g_Vt + (((size_t)(b*HH + hh))*8 + tile)*8192
                                  + (size_t)kk*256 + sl;
                *(uint4*)vp         = hi;
                *(uint4*)(vp + 128) = lo;
            }
        }
    }
    __syncthreads();
    if (wid == 0) TCGEN05_DEALLOC(tmem, 256);
#endif
}

// ---------------------------------------------------------------------------
// Attention: R12 exact (best-known schedule; attn 298us).
// ---------------------------------------------------------------------------
#define SM_Q    0
#define SM_K0   16384
#define SM_K1   32768
#define SM_V0   49152
#define SM_V1   65536
#define SM_P    81920
#define SM_MSK  147456
#define SM_RED  151552
#define SM_LIV  153600
#define SM_MBA  154112
#define SM_MBB  154120
#define SM_TM   154128
#define SMEM_ATTN 154144

__global__ __launch_bounds__(512, 1) void attn_kernel(
    const float* __restrict__ mask, float* __restrict__ out)
{
    extern __shared__ char smc[];
    const int tid  = threadIdx.x;
    const int qb = blockIdx.x, h = blockIdx.y, b = blockIdx.z;

#if TC_PATH
    const uint32_t smb = smem_u32(smc);
    const int wid  = tid >> 5;
    const int lane = tid & 31;
    const int r  = (wid & 3)*32 + lane;
    const int c0 = (wid >> 2)*32;

    if (wid == 0) TCGEN05_ALLOC(smb + SM_TM, 512);
    if (tid == 0) { MBARRIER_INIT(smb + SM_MBA, 1); MBARRIER_INIT(smb + SM_MBB, 1); }

    const size_t bh = (size_t)(b*HH + h);
    const uint4* qg = (const uint4*)(g_Qs + bh*(SS*64) + (size_t)qb*128*64);
    const __nv_bfloat16* kgb = g_Ksx + bh*(SS*64);
    const __nv_bfloat16* vgb = g_Vt  + bh*(8*32*256);

    const int it0 = tid, it1 = tid + 512;
    const int k_rr0 = it0 >> 3, k_ch0 = it0 & 7;
    const int k_rr1 = it1 >> 3, k_ch1 = it1 & 7;
    const int v_n0 = it0 >> 5, v_c0 = (it0 & 31)*8;
    const int v_n1 = it1 >> 5, v_c1 = (it1 & 31)*8;

    for (int it = tid; it < 1024; it += 512) {
        int rr = it >> 3, ch = it & 7;
        *(uint4*)(smc + SM_Q + sw128(rr*128 + ch*16)) = qg[it];
    }
    if (tid < 256) ((uint4*)(smc + SM_MSK))[tid] = ((const uint4*)(mask + (size_t)b*SS))[tid];
    {
        const uint4* kg = (const uint4*)(kgb);
        const uint4* vg = (const uint4*)(vgb);
        *(uint4*)(smc + SM_K0 + sw128(k_rr0*128 + k_ch0*16)) = kg[it0];
        *(uint4*)(smc + SM_K0 + sw128(k_rr1*128 + k_ch1*16)) = kg[it1];
        *(uint4*)(smc + SM_V0 + v_off(v_n0, v_c0)) = vg[it0];
        *(uint4*)(smc + SM_V0 + v_off(v_n1, v_c1)) = vg[it1];
    }
    FENCE_ASYNC_SHARED();
    __syncthreads();

    uint32_t tmem;
    asm volatile("ld.shared.b32 %0, [%1];" : "=r"(tmem) : "r"(smb + SM_TM));
    const uint32_t dS[2] = { tmem, tmem + 128 };
    const uint32_t dO = tmem + 256;

    const float* Msk = (const float*)(smc + SM_MSK);
    const uint64_t qdesc = MAKE_DESC(smb + SM_Q);
    const uint64_t pdesc = MAKE_DESC(smb + SM_P);
    const uint64_t kdesc[2] = { MAKE_DESC(smb + SM_K0), MAKE_DESC(smb + SM_K1) };
    const uint64_t vdesc[2] = { MAKE_DESC(smb + SM_V0), MAKE_DESC(smb + SM_V1) };
    const uint32_t smKoff[2] = { SM_K0, SM_K1 };
    const uint32_t smVoff[2] = { SM_V0, SM_V1 };

    if (wid == 0 && elect_one()) {
        issue_qk(dS[0], qdesc, kdesc[0], smb + SM_MBA);
    }

    int cntA = 0, cntB = 0;
    float lacc = 0.0f;

    for (int kt = 0; kt < 8; kt++) {
        const int buf = kt & 1, nbuf = buf ^ 1;

        uint4 kreg0, kreg1, vreg0, vreg1;
        if (kt + 1 < 8) {
            const uint4* kg = (const uint4*)(kgb + (size_t)(kt + 1)*128*64);
            const uint4* vg = (const uint4*)(vgb + (size_t)(kt + 1)*32*256);
            kreg0 = kg[it0]; kreg1 = kg[it1];
            vreg0 = vg[it0]; vreg1 = vg[it1];
        }

        MBARRIER_WAIT_PARITY(smb + SM_MBA, cntA & 1); cntA++;
        TCGEN05_FENCE_AFTER();

        uint32_t sregs[32];
        TCGEN05_LD_X32(sregs, dS[buf] + c0);
        TCGEN05_WAIT_LD();

        float p[32];
        #pragma unroll
        for (int j = 0; j < 32; j++) {
            float m  = Msk[kt*128 + c0 + j];
            float sv = fmaf(m, __uint_as_float(sregs[j]), (m - 1.0f)*1e-30f);
            p[j] = __expf(sv - 40.0f);
            lacc += p[j];
        }

        if (kt) { MBARRIER_WAIT_PARITY(smb + SM_MBB, cntB & 1); cntB++; }

        if (kt + 1 < 8) {
            *(uint4*)(smc + smKoff[nbuf] + sw128(k_rr0*128 + k_ch0*16)) = kreg0;
            *(uint4*)(smc + smKoff[nbuf] + sw128(k_rr1*128 + k_ch1*16)) = kreg1;
            *(uint4*)(smc + smVoff[nbuf] + v_off(v_n0, v_c0)) = vreg0;
            *(uint4*)(smc + smVoff[nbuf] + v_off(v_n1, v_c1)) = vreg1;
        }

        #pragma unroll
        for (int g = 0; g < 4; g++) {
            uint32_t hp[4], lp[4];
            #pragma unroll
            for (int q = 0; q < 4; q++) {
                float a0 = p[g*8 + 2*q], a1 = p[g*8 + 2*q + 1];
                __nv_bfloat162 hh = __floats2bfloat162_rn(a0, a1);
                float h0 = __low2float(hh), h1 = __high2float(hh);
                __nv_bfloat162 ll = __floats2bfloat162_rn(a0 - h0, a1 - h1);
                hp[q] = bf2u(hh); lp[q] = bf2u(ll);
            }
            *(uint4*)(smc + SM_P + p_off(r, c0 + g*8))       = make_uint4(hp[0], hp[1], hp[2], hp[3]);
            *(uint4*)(smc + SM_P + p_off(r, 128 + c0 + g*8)) = make_uint4(lp[0], lp[1], lp[2], lp[3]);
        }

        FENCE_ASYNC_SHARED();
        __syncthreads();

        if (wid == 0 && elect_one()) {
            if (kt + 1 < 8)
                issue_qk(dS[nbuf], qdesc, kdesc[nbuf], smb + SM_MBA);
            issue_pv(dO, pdesc, vdesc[buf], kt == 0, smb + SM_MBB);
        }
    }
    MBARRIER_WAIT_PARITY(smb + SM_MBB, cntB & 1); cntB++;
    TCGEN05_FENCE_AFTER();

    ((float*)(smc + SM_RED))[(wid >> 2)*128 + r] = lacc;
    __syncthreads();
    if (tid < 128) {
        const float* rd = (const float*)(smc + SM_RED);
        ((float*)(smc + SM_LIV))[tid] =
            1.0f / (rd[tid] + rd[128 + tid] + rd[256 + tid] + rd[384 + tid]);
    }
    __syncthreads();

    if (wid < 4) {
        uint32_t oregs[32];
        TCGEN05_LD_X32(oregs, dO);
        TCGEN05_WAIT_LD();
        float inv = ((float*)(smc + SM_LIV))[r];
        float* op = out + (((size_t)b*SS) + qb*128 + r)*256 + h*32;
        #pragma unroll
        for (int g = 0; g < 8; g++) {
            float4 v;
            v.x = __uint_as_float(oregs[g*4+0])*inv;
            v.y = __uint_as_float(oregs[g*4+1])*inv;
            v.z = __uint_as_float(oregs[g*4+2])*inv;
            v.w = __uint_as_float(oregs[g*4+3])*inv;
            *(float4*)(op + g*4) = v;
        }
    }
    __syncthreads();
    if (wid == 0) TCGEN05_DEALLOC(tmem, 512);

#else  // ===================== baseline FFMA flash (512 threads) =====================
    float* sm = (float*)smc;
    float* Qt = sm;
    float* Kt = Qt + 32*132;
    float* Vs = Kt + 32*68;
    float* Ps = Vs + 64*32;
    float* Ms = Ps + 128*68;

    const int tx = tid & 15, ty = tid >> 4;

    const float* qptr = g_q + (((size_t)(b*HH + h))*SS + qb*128)*DKK;
    for (int idx = tid; idx < 128*32; idx += 512) {
        int d = idx & 31, rr = idx >> 5;
        Qt[d*132 + rr] = qptr[idx];
    }

    float m_i[4], l_i[4], o0[4], o1[4];
    #pragma unroll
    for (int i = 0; i < 4; i++) { m_i[i] = -1e38f; l_i[i] = 0.f; o0[i] = 0.f; o1[i] = 0.f; }

    const float* kbase = g_k + ((size_t)(b*HH + h))*SS*DKK;
    const float* vbase = g_v + ((size_t)(b*HH + h))*SS*DKK;
    const float* mbase = mask + (size_t)b*SS;

    for (int kt = 0; kt < 16; kt++) {
        __syncthreads();
        const float* kp = kbase + (size_t)kt*64*32;
        for (int idx = tid; idx < 64*32; idx += 512) {
            int d = idx & 31, rr = idx >> 5;
            Kt[d*68 + rr] = kp[idx];
        }
        const float4* vp = (const float4*)(vbase + (size_t)kt*64*32);
        for (int idx = tid; idx < 64*32/4; idx += 512)
            ((float4*)Vs)[idx] = vp[idx];
        if (tid < 64) Ms[tid] = mbase[kt*64 + tid];
        __syncthreads();

        float sc[4][4];
        #pragma unroll
        for (int i = 0; i < 4; i++)
            #pragma unroll
            for (int j = 0; j < 4; j++) sc[i][j] = 0.f;

        #pragma unroll 8
        for (int d = 0; d < 32; d++) {
            float a[4], kv[4];
            *(float4*)&a[0]  = *(float4*)&Qt[d*132 + ty*4];
            *(float4*)&kv[0] = *(float4*)&Kt[d*68 + tx*4];
            #pragma unroll
            for (int i = 0; i < 4; i++)
                #pragma unroll
                for (int j = 0; j < 4; j++)
                    sc[i][j] += a[i]*kv[j];
        }

        float mv[4];
        #pragma unroll
        for (int j = 0; j < 4; j++) mv[j] = Ms[tx*4 + j];

        #pragma unroll
        for (int i = 0; i < 4; i++) {
            #pragma unroll
            for (int j = 0; j < 4; j++)
                sc[i][j] = mv[j]*sc[i][j] + (1.f - mv[j])*(-1e-30f);

            float tm = fmaxf(fmaxf(sc[i][0], sc[i][1]), fmaxf(sc[i][2], sc[i][3]));
            #pragma unroll
            for (int off = 8; off > 0; off >>= 1)
                tm = fmaxf(tm, __shfl_xor_sync(0xffffffffu, tm, off));

            float mnew = fmaxf(m_i[i], tm);
            float rs = 0.f;
            #pragma unroll
            for (int j = 0; j < 4; j++) {
                float pp = __expf(sc[i][j] - mnew);
                sc[i][j] = pp;
                rs += pp;
            }
            #pragma unroll
            for (int off = 8; off > 0; off >>= 1)
                rs += __shfl_xor_sync(0xffffffffu, rs, off);

            float alpha = __expf(m_i[i] - mnew);
            l_i[i] = l_i[i]*alpha + rs;
            m_i[i] = mnew;
            o0[i] *= alpha;
            o1[i] *= alpha;

            *(float4*)&Ps[(ty*4+i)*68 + tx*4] =
                make_float4(sc[i][0], sc[i][1], sc[i][2], sc[i][3]);
        }
        __syncthreads();

        #pragma unroll 4
        for (int s0 = 0; s0 < 64; s0 += 4) {
            float2 v0 = *(float2*)&Vs[(s0+0)*32 + tx*2];
            float2 v1 = *(float2*)&Vs[(s0+1)*32 + tx*2];
            float2 v2 = *(float2*)&Vs[(s0+2)*32 + tx*2];
            float2 v3 = *(float2*)&Vs[(s0+3)*32 + tx*2];
            #pragma unroll
            for (int i = 0; i < 4; i++) {
                float4 pp = *(float4*)&Ps[(ty*4+i)*68 + s0];
                o0[i] += pp.x*v0.x + pp.y*v1.x + pp.z*v2.x + pp.w*v3.x;
                o1[i] += pp.x*v0.y + pp.y*v1.y + pp.z*v2.y + pp.w*v3.y;
            }
        }
    }

    #pragma unroll
    for (int i = 0; i < 4; i++) {
        float inv = 1.f / l_i[i];
        int row = qb*128 + ty*4 + i;
        float2 res = make_float2(o0[i]*inv, o1[i]*inv);
        *(float2*)&out[((size_t)b*SS + row)*256 + h*32 + tx*2] = res;
    }
#endif
}

// ---------------------------------------------------------------------------
extern "C" void kernel_launch(void* const* d_in, const int* in_sizes, int n_in,
                              void* d_out, int out_size)
{
    (void)in_sizes; (void)n_in; (void)out_size;
    const float* query = (const float*)d_in[0];
    const float* key   = (const float*)d_in[1];
    const float* value = (const float*)d_in[2];
    const float* mask  = (const float*)d_in[3];
    const float* Wq    = (const float*)d_in[4];
    const float* Wk    = (const float*)d_in[5];
    const float* Wv    = (const float*)d_in[6];
    float* out = (float*)d_out;

    cudaFuncSetAttribute(attn_kernel,
                         cudaFuncAttributeMaxDynamicSharedMemorySize, SMEM_ATTN);
    cudaFuncSetAttribute(proj2_kernel,
                         cudaFuncAttributeMaxDynamicSharedMemorySize, SMEM_PJ);

    proj_kernel<<<dim3(256, 2, 3), 256>>>(query, key, value, Wq, Wk, Wv);
    proj2_kernel<<<dim3(128, 2, 3), 512, SMEM_PJ>>>(query, key, value, Wq, Wk, Wv);
    attn_kernel<<<dim3(8, 8, 32), 512, SMEM_ATTN>>>(mask, out);
}